// round 14
// baseline (speedup 1.0000x reference)
#include <cuda_runtime.h>
#include <math.h>
#include <stdint.h>

// ---------------- constants ----------------
#define TKN 512
#define DIM 512
#define CCH 256
#define HGT 128
#define WID 128
#define PPT 36
#define PGN 128
#define TOTN 66832
#define CC2 65536

// ---------------- scratch ----------------
__device__ float g_imgT[8 * HGT * WID * CCH];
__device__ float g_hidden[TKN * PGN];
__device__ float g_grid[TKN * PPT * 2];
__device__ float g_params[(size_t)TKN * TOTN];
__device__ float g_sampled[TKN * PPT * CCH];
__device__ float g_h[TKN * PPT * CCH];
__device__ float g_tok[TKN * DIM];
__device__ float g_tok2[TKN * DIM];
__device__ float g_x[TKN * DIM];
__device__ float g_qkv[TKN * 3 * DIM];
__device__ float g_attout[TKN * DIM];
__device__ float g_ff[TKN * 4 * DIM];

__device__ __forceinline__ float gelu_f(float x) {
    return 0.5f * x * (1.0f + erff(x * 0.70710678118654752440f));
}
__device__ __forceinline__ float f2tf32f(float x) {
    uint32_t r;
    asm("cvt.rna.tf32.f32 %0, %1;" : "=r"(r) : "f"(x));
    return __uint_as_float(r);
}
__device__ __forceinline__ void red2f(float* p, float a, float b) {
    asm volatile("red.global.add.v2.f32 [%0], {%1, %2};"
                 :: "l"(p), "f"(a), "f"(b) : "memory");
}

// ---------------- img transpose ----------------
__global__ void transpose_k(const float* __restrict__ in) {
    __shared__ float tile[32][33];
    int b = blockIdx.z;
    int s0 = blockIdx.x * 32;
    int c0 = blockIdx.y * 32;
    const float* ib = in + (size_t)b * CCH * HGT * WID;
    float* ob = g_imgT + (size_t)b * HGT * WID * CCH;
    int tid = threadIdx.x;
    {
        int c = tid >> 3, s4 = tid & 7;
        float4 v = *(const float4*)(ib + (size_t)(c0 + c) * (HGT * WID) + s0 + 4 * s4);
        tile[4 * s4 + 0][c] = v.x;
        tile[4 * s4 + 1][c] = v.y;
        tile[4 * s4 + 2][c] = v.z;
        tile[4 * s4 + 3][c] = v.w;
    }
    __syncthreads();
    {
        int g = tid & 7, s = tid >> 3;
        float4 v;
        v.x = tile[s][4 * g + 0];
        v.y = tile[s][4 * g + 1];
        v.z = tile[s][4 * g + 2];
        v.w = tile[s][4 * g + 3];
        *(float4*)(ob + (size_t)(s0 + s) * CCH + c0 + 4 * g) = v;
    }
}

// ---------------- per-token pre ----------------
__global__ void pre_k(const float* __restrict__ x, const float* __restrict__ roi,
                      const float* __restrict__ g_off, const float* __restrict__ b_off,
                      const float* __restrict__ w_off, const float* __restrict__ off_bias,
                      const float* __restrict__ g_pg, const float* __restrict__ b_pg,
                      const float* __restrict__ w_pg1, const float* __restrict__ b_pg1) {
    int t = blockIdx.x;
    int tid = threadIdx.x;
    __shared__ float xoff[DIM], xpg[DIM], offs[72];
    __shared__ float rs[4], rs2[4], stats[4];

    const float* xr = x + (size_t)t * DIM;
    float v[4], s = 0.f, s2 = 0.f;
#pragma unroll
    for (int i = 0; i < 4; i++) { v[i] = xr[tid + 128 * i]; s += v[i]; s2 += v[i] * v[i]; }
#pragma unroll
    for (int o = 16; o; o >>= 1) {
        s  += __shfl_down_sync(0xffffffffu, s,  o);
        s2 += __shfl_down_sync(0xffffffffu, s2, o);
    }
    if ((tid & 31) == 0) { rs[tid >> 5] = s; rs2[tid >> 5] = s2; }
    __syncthreads();
    float ts = rs[0] + rs[1] + rs[2] + rs[3];
    float ts2 = rs2[0] + rs2[1] + rs2[2] + rs2[3];
    float mean = ts * (1.f / DIM);
    float var = ts2 * (1.f / DIM) - mean * mean;
    float rstd = rsqrtf(var + 1e-5f);
#pragma unroll
    for (int i = 0; i < 4; i++) {
        int k = tid + 128 * i;
        float xn = (v[i] - mean) * rstd;
        xoff[k] = xn * g_off[k] + b_off[k];
        xpg[k]  = xn * g_pg[k]  + b_pg[k];
    }
    __syncthreads();

    {
        float h = b_pg1[tid];
        for (int k = 0; k < DIM; k++) h = fmaf(xpg[k], w_pg1[k * PGN + tid], h);
        g_hidden[t * PGN + tid] = f2tf32f(h);
    }
    if (tid < 72) {
        float o = off_bias[tid];
        for (int k = 0; k < DIM; k++) o = fmaf(xoff[k], w_off[k * 72 + tid], o);
        offs[tid] = o;
    }
    __syncthreads();
    if (tid < 2) {
        float mu = 0.f;
        for (int p = 0; p < PPT; p++) mu += offs[p * 2 + tid];
        mu *= (1.f / PPT);
        float vv = 0.f;
        for (int p = 0; p < PPT; p++) { float d = offs[p * 2 + tid] - mu; vv += d * d; }
        vv *= (1.f / (PPT - 1));
        stats[tid * 2] = mu;
        stats[tid * 2 + 1] = sqrtf(vv) + 1e-5f;
    }
    __syncthreads();
    if (tid < 72) {
        int coord = tid & 1, p = tid >> 1;
        float mu = stats[coord * 2], sd = stats[coord * 2 + 1];
        float on = (offs[tid] - mu) / (3.f * sd);
        float tl = roi[t * 4 + coord], br = roi[t * 4 + 2 + coord];
        float xy = 0.5f * (tl + br), wh = br - tl;
        float pt = xy + on * wh;
        g_grid[(t * PPT + p) * 2 + coord] = pt * 2.f - 1.f;
    }
}

// ---------------- bilinear grid sample ----------------
__global__ void sample_k() {
    int p = blockIdx.x, t = blockIdx.y;
    int c4 = threadIdx.x << 2;
    int b = t >> 6;
    float gx = g_grid[(t * PPT + p) * 2 + 0];
    float gy = g_grid[(t * PPT + p) * 2 + 1];
    float x = ((gx + 1.f) * WID - 1.f) * 0.5f;
    float y = ((gy + 1.f) * HGT - 1.f) * 0.5f;
    float x0f = floorf(x), y0f = floorf(y);
    float wx = x - x0f, wy = y - y0f;
    int x0 = min(max((int)x0f, 0), WID - 1);
    int x1 = min(max((int)x0f + 1, 0), WID - 1);
    int y0 = min(max((int)y0f, 0), HGT - 1);
    int y1 = min(max((int)y0f + 1, 0), HGT - 1);
    const float* ib = g_imgT + (size_t)b * HGT * WID * CCH;
    float4 v00 = *(const float4*)(ib + (size_t)(y0 * WID + x0) * CCH + c4);
    float4 v01 = *(const float4*)(ib + (size_t)(y0 * WID + x1) * CCH + c4);
    float4 v10 = *(const float4*)(ib + (size_t)(y1 * WID + x0) * CCH + c4);
    float4 v11 = *(const float4*)(ib + (size_t)(y1 * WID + x1) * CCH + c4);
    float w00 = (1.f - wx) * (1.f - wy), w01 = wx * (1.f - wy);
    float w10 = (1.f - wx) * wy,         w11 = wx * wy;
    float4 o;
    o.x = v00.x * w00 + v01.x * w01 + v10.x * w10 + v11.x * w11;
    o.y = v00.y * w00 + v01.y * w01 + v10.y * w10 + v11.y * w11;
    o.z = v00.z * w00 + v01.z * w01 + v10.z * w10 + v11.z * w11;
    o.w = v00.w * w00 + v01.w * w01 + v10.w * w10 + v11.w * w11;
    *(float4*)(g_sampled + ((size_t)t * PPT + p) * CCH + c4) = o;
}

// ---------------- cp.async helpers ----------------
__device__ __forceinline__ void cpa16(uint32_t dst, const void* src, bool pred) {
    int sz = pred ? 16 : 0;
    asm volatile("cp.async.cg.shared.global [%0], [%1], 16, %2;"
                 :: "r"(dst), "l"(src), "r"(sz));
}
__device__ __forceinline__ void cpa_commit() {
    asm volatile("cp.async.commit_group;");
}
__device__ __forceinline__ uint32_t smem_u32(const void* p) {
    uint32_t a;
    asm("{ .reg .u64 t; cvta.to.shared.u64 t, %1; cvt.u32.u64 %0, t; }" : "=r"(a) : "l"(p));
    return a;
}

// ---------------- templated tf32 GEMM: TM*64-row x TN*16-col tile ----------------
// 3-buffer cp.async pipeline, 1 barrier/ktile. Raw fp32 B (HW tf32 truncation).
template <int TM, int TN>
__global__ void __launch_bounds__(256)
mma_gemm_t(const float* __restrict__ A, const float* __restrict__ Bm,
           const float* __restrict__ bias, float* __restrict__ C,
           int M, int N, int K, int rnd, int act) {
    constexpr int AROWS = TM * 64;        // 128 or 256
    constexpr int ASZf  = AROWS * 36;
    constexpr int AIT   = AROWS / 32;     // A-load iters (4 or 8)
    constexpr int BN    = TN * 16;
    constexpr int BSTR  = BN + 8;
    constexpr int BSZf  = 32 * BSTR;
    constexpr int STGf  = ASZf + BSZf;
    constexpr int BIT   = BN / 32;
    constexpr int BQ    = BN / 4;

    extern __shared__ float smf[];
    uint32_t sbase = smem_u32(smf);

    int tid = threadIdx.x;
    int warp = tid >> 5, lane = tid & 31;
    int wr = (warp >> 1) * (TM * 16);
    int wc = (warp & 1) * (TN * 8);
    int bR = blockIdx.y * AROWS, bC = blockIdx.x * BN;
    int nz = gridDim.z;
    int Kc = K / nz;
    int kbeg = blockIdx.z * Kc;
    int ntiles = Kc >> 5;

    float acc[TM][TN][4];
#pragma unroll
    for (int a = 0; a < TM; a++)
#pragma unroll
        for (int b = 0; b < TN; b++)
#pragma unroll
            for (int c = 0; c < 4; c++) acc[a][b][c] = 0.f;

    int ar[AIT], ac[AIT];
#pragma unroll
    for (int i = 0; i < AIT; i++) {
        int f = tid + (i << 8);
        ar[i] = f >> 3;  ac[i] = (f & 7) << 2;
    }
    int br_[BIT], bc_[BIT];
#pragma unroll
    for (int i = 0; i < BIT; i++) {
        int f = tid + (i << 8);
        br_[i] = f / BQ; bc_[i] = (f % BQ) << 2;
    }

    auto issue = [&](int t, int stage) {
        int k0 = kbeg + (t << 5);
        uint32_t sa = sbase + stage * (STGf * 4);
#pragma unroll
        for (int i = 0; i < AIT; i++) {
            cpa16(sa + (ar[i] * 36 + ac[i]) * 4,
                  A + (size_t)(bR + ar[i]) * K + k0 + ac[i], true);
        }
        uint32_t sb = sa + ASZf * 4;
#pragma unroll
        for (int i = 0; i < BIT; i++) {
            int gc = bC + bc_[i];
            cpa16(sb + (br_[i] * BSTR + bc_[i]) * 4,
                  Bm + (size_t)(k0 + br_[i]) * N + gc, gc < N);
        }
        cpa_commit();
    };

    issue(0, 0);
    if (ntiles > 1) issue(1, 1);
    int rd = 0;
    int wrb = 2;
    for (int t = 0; t < ntiles; t++) {
        if (t + 1 < ntiles) {
            asm volatile("cp.async.wait_group 1;");
        } else {
            asm volatile("cp.async.wait_group 0;");
        }
        __syncthreads();
        if (t + 2 < ntiles) {
            issue(t + 2, wrb);
            wrb = (wrb == 2) ? 0 : wrb + 1;
        }
        const uint32_t* As = (const uint32_t*)(smf + rd * STGf);
        const uint32_t* Bs = As + ASZf;
        rd = (rd == 2) ? 0 : rd + 1;
#pragma unroll
        for (int k8 = 0; k8 < 4; k8++) {
            int kk = k8 << 3;
            uint32_t afr[TM][4];
#pragma unroll
            for (int tm = 0; tm < TM; tm++) {
                int r = wr + tm * 16 + (lane >> 2);
                int c = kk + (lane & 3);
                afr[tm][0] = As[r * 36 + c];
                afr[tm][1] = As[(r + 8) * 36 + c];
                afr[tm][2] = As[r * 36 + c + 4];
                afr[tm][3] = As[(r + 8) * 36 + c + 4];
            }
#pragma unroll
            for (int tn = 0; tn < TN; tn++) {
                int col = wc + tn * 8 + (lane >> 2);
                uint32_t b0 = Bs[(kk + (lane & 3)) * BSTR + col];
                uint32_t b1 = Bs[(kk + (lane & 3) + 4) * BSTR + col];
#pragma unroll
                for (int tm = 0; tm < TM; tm++) {
                    asm volatile(
                        "mma.sync.aligned.m16n8k8.row.col.f32.tf32.tf32.f32 "
                        "{%0,%1,%2,%3}, {%4,%5,%6,%7}, {%8,%9}, {%0,%1,%2,%3};"
                        : "+f"(acc[tm][tn][0]), "+f"(acc[tm][tn][1]),
                          "+f"(acc[tm][tn][2]), "+f"(acc[tm][tn][3])
                        : "r"(afr[tm][0]), "r"(afr[tm][1]),
                          "r"(afr[tm][2]), "r"(afr[tm][3]),
                          "r"(b0), "r"(b1));
                }
            }
        }
    }

    if (nz == 1) {
#pragma unroll
        for (int tm = 0; tm < TM; tm++) {
            int row = bR + wr + tm * 16 + (lane >> 2);
#pragma unroll
            for (int tn = 0; tn < TN; tn++) {
                int col = bC + wc + tn * 8 + ((lane & 3) << 1);
                if (col >= N) continue;
                float bv0 = 0.f, bv1 = 0.f;
                if (bias) { bv0 = bias[col]; bv1 = bias[col + 1]; }
                float o0 = acc[tm][tn][0] + bv0, o1 = acc[tm][tn][1] + bv1;
                float o2 = acc[tm][tn][2] + bv0, o3 = acc[tm][tn][3] + bv1;
                if (act) {
                    o0 = gelu_f(o0); o1 = gelu_f(o1);
                    o2 = gelu_f(o2); o3 = gelu_f(o3);
                }
                if (rnd | act) {
                    o0 = f2tf32f(o0); o1 = f2tf32f(o1);
                    o2 = f2tf32f(o2); o3 = f2tf32f(o3);
                }
                *(float2*)(&C[(size_t)row * N + col])       = make_float2(o0, o1);
                *(float2*)(&C[(size_t)(row + 8) * N + col]) = make_float2(o2, o3);
            }
        }
    } else {
#pragma unroll
        for (int tm = 0; tm < TM; tm++) {
            int row = bR + wr + tm * 16 + (lane >> 2);
#pragma unroll
            for (int tn = 0; tn < TN; tn++) {
                int col = bC + wc + tn * 8 + ((lane & 3) << 1);
                red2f(&C[(size_t)row * N + col], acc[tm][tn][0], acc[tm][tn][1]);
                red2f(&C[(size_t)(row + 8) * N + col], acc[tm][tn][2], acc[tm][tn][3]);
            }
        }
    }
}

// ---------------- init ----------------
__global__ void init_k(const float* __restrict__ resid, const float* __restrict__ bias,
                       float* __restrict__ C, int n, int N) {
    int i = blockIdx.x * 256 + threadIdx.x;
    if (i < n) {
        int col = i % N;
        C[i] = (resid ? resid[i] : 0.f) + bias[col];
    }
}

// ---------------- tensor-core per-token mixing ----------------
#define MIX_ASTR 260
#define MIX_BSTR 264
#define MIX_AF (48 * MIX_ASTR)
#define MIX_BF (32 * MIX_BSTR)
#define MIX_SMF (MIX_AF + 2 * MIX_BF + 1296)
__global__ void __launch_bounds__(256)
mixmma_k(const float* __restrict__ mb, const float* __restrict__ sb) {
    extern __shared__ float smf[];
    float* Aa  = smf;
    float* Bb  = smf + MIX_AF;
    float* sms = smf + MIX_AF + 2 * MIX_BF;
    uint32_t sbase = smem_u32(smf);

    int t = blockIdx.x, tid = threadIdx.x;
    int warp = tid >> 5, lane = tid & 31;
    const float* pt = g_params + (size_t)t * TOTN;

    for (int i = tid; i < 12 * MIX_ASTR; i += 256) Aa[36 * MIX_ASTR + i] = 0.f;
    const float4* sp4 = (const float4*)(g_sampled + (size_t)t * (PPT * CCH));
    for (int i = tid; i < PPT * CCH / 4; i += 256) {
        float4 v = sp4[i];
        int r = i >> 6, c = (i & 63) << 2;
        float* d = Aa + r * MIX_ASTR + c;
        d[0] = f2tf32f(v.x); d[1] = f2tf32f(v.y);
        d[2] = f2tf32f(v.z); d[3] = f2tf32f(v.w);
    }
    for (int i = tid; i < PPT * PPT; i += 256) sms[i] = pt[CC2 + i];

    uint32_t bB = sbase + MIX_AF * 4;
    auto issue = [&](int ch, int stg) {
        const float* src = pt + ch * 32 * 256;
        uint32_t dst = bB + stg * (MIX_BF * 4);
#pragma unroll
        for (int i = 0; i < 8; i++) {
            int e = tid + (i << 8);
            int r = e >> 6, c4 = (e & 63) << 2;
            cpa16(dst + (r * MIX_BSTR + c4) * 4, src + r * 256 + c4, true);
        }
        cpa_commit();
    };

    float acc[3][4][4];
#pragma unroll
    for (int a = 0; a < 3; a++)
#pragma unroll
        for (int b = 0; b < 4; b++)
#pragma unroll
            for (int c = 0; c < 4; c++) acc[a][b][c] = 0.f;

    issue(0, 0);
    for (int ch = 0; ch < 8; ch++) {
        if (ch + 1 < 8) {
            issue(ch + 1, (ch + 1) & 1);
            asm volatile("cp.async.wait_group 1;");
        } else {
            asm volatile("cp.async.wait_group 0;");
        }
        __syncthreads();
        const uint32_t* As = (const uint32_t*)Aa;
        const uint32_t* Bs = (const uint32_t*)(Bb + (ch & 1) * MIX_BF);
#pragma unroll
        for (int k8 = 0; k8 < 4; k8++) {
            int kk = (ch << 5) + (k8 << 3);
            int kb = k8 << 3;
            uint32_t afr[3][4];
#pragma unroll
            for (int mt = 0; mt < 3; mt++) {
                int r = mt * 16 + (lane >> 2);
                int c = kk + (lane & 3);
                afr[mt][0] = As[r * MIX_ASTR + c];
                afr[mt][1] = As[(r + 8) * MIX_ASTR + c];
                afr[mt][2] = As[r * MIX_ASTR + c + 4];
                afr[mt][3] = As[(r + 8) * MIX_ASTR + c + 4];
            }
#pragma unroll
            for (int tn = 0; tn < 4; tn++) {
                int col = warp * 32 + tn * 8 + (lane >> 2);
                uint32_t b0 = Bs[(kb + (lane & 3)) * MIX_BSTR + col];
                uint32_t b1 = Bs[(kb + (lane & 3) + 4) * MIX_BSTR + col];
#pragma unroll
                for (int mt = 0; mt < 3; mt++) {
                    asm volatile(
                        "mma.sync.aligned.m16n8k8.row.col.f32.tf32.tf32.f32 "
                        "{%0,%1,%2,%3}, {%4,%5,%6,%7}, {%8,%9}, {%0,%1,%2,%3};"
                        : "+f"(acc[mt][tn][0]), "+f"(acc[mt][tn][1]),
                          "+f"(acc[mt][tn][2]), "+f"(acc[mt][tn][3])
                        : "r"(afr[mt][0]), "r"(afr[mt][1]),
                          "r"(afr[mt][2]), "r"(afr[mt][3]),
                          "r"(b0), "r"(b1));
                }
            }
        }
        __syncthreads();
    }

    float* hsh = Bb;
#pragma unroll
    for (int mt = 0; mt < 3; mt++) {
#pragma unroll
        for (int half = 0; half < 2; half++) {
            int row = mt * 16 + (lane >> 2) + half * 8;
            if (row >= PPT) continue;
#pragma unroll
            for (int tn = 0; tn < 4; tn++) {
                int col = warp * 32 + tn * 8 + ((lane & 3) << 1);
                hsh[row * 260 + col]     = gelu_f(acc[mt][tn][half * 2 + 0] + mb[col]);
                hsh[row * 260 + col + 1] = gelu_f(acc[mt][tn][half * 2 + 1] + mb[col + 1]);
            }
        }
    }
    __syncthreads();

    int d4 = tid & 63;
    int q0 = (tid >> 6) * 9;
    float4 accq[9];
#pragma unroll
    for (int q = 0; q < 9; q++) {
        float s = sb[q0 + q];
        accq[q] = make_float4(s, s, s, s);
    }
    for (int p = 0; p < PPT; p++) {
        float4 hv = *(const float4*)(hsh + p * 260 + 4 * d4);
#pragma unroll
        for (int q = 0; q < 9; q++) {
            float smv = sms[(q0 + q) * PPT + p];
            accq[q].x = fmaf(smv, hv.x, accq[q].x);
            accq[q].y = fmaf(smv, hv.y, accq[q].y);
            accq[q].z = fmaf(smv, hv.z, accq[q].z);
            accq[q].w = fmaf(smv, hv.w, accq[q].w);
        }
    }
    float* ho = g_h + (size_t)t * (PPT * CCH);
#pragma unroll
    for (int q = 0; q < 9; q++) {
        float4 o;
        o.x = f2tf32f(gelu_f(accq[q].x));
        o.y = f2tf32f(gelu_f(accq[q].y));
        o.z = f2tf32f(gelu_f(accq[q].z));
        o.w = f2tf32f(gelu_f(accq[q].w));
        *(float4*)(ho + (q0 + q) * CCH + 4 * d4) = o;
    }
}

// ---------------- layernorm ----------------
__global__ void ln_k(const float* __restrict__ x, const float* __restrict__ g,
                     const float* __restrict__ bb, float* __restrict__ y) {
    int t = blockIdx.x, tid = threadIdx.x;
    __shared__ float rs[4], rs2[4];
    const float* xr = x + (size_t)t * DIM;
    float v[4], s = 0.f, s2 = 0.f;
#pragma unroll
    for (int i = 0; i < 4; i++) { v[i] = xr[tid + 128 * i]; s += v[i]; s2 += v[i] * v[i]; }
#pragma unroll
    for (int o = 16; o; o >>= 1) {
        s  += __shfl_down_sync(0xffffffffu, s,  o);
        s2 += __shfl_down_sync(0xffffffffu, s2, o);
    }
    if ((tid & 31) == 0) { rs[tid >> 5] = s; rs2[tid >> 5] = s2; }
    __syncthreads();
    float ts = rs[0] + rs[1] + rs[2] + rs[3];
    float ts2 = rs2[0] + rs2[1] + rs2[2] + rs2[3];
    float mean = ts * (1.f / DIM);
    float var = ts2 * (1.f / DIM) - mean * mean;
    float rstd = rsqrtf(var + 1e-5f);
#pragma unroll
    for (int i = 0; i < 4; i++) {
        int k = tid + 128 * i;
        y[(size_t)t * DIM + k] = f2tf32f((v[i] - mean) * rstd * g[k] + bb[k]);
    }
}

// ---------------- attention v2 ----------------
__global__ void __launch_bounds__(128) attn_k() {
    extern __shared__ float asm_[];
    float* Ks  = asm_;
    float* Vs  = asm_ + 4096;
    float* scp = asm_ + 8192;

    int b = blockIdx.x, h = blockIdx.y;
    int tid = threadIdx.x;
    int q = tid & 63, half = tid >> 6;
    const float* base = g_qkv + (size_t)b * 64 * (3 * DIM);
    for (int i = tid; i < 64 * 64; i += 128) {
        int n = i >> 6, d2 = i & 63;
        Ks[i] = base[(size_t)n * (3 * DIM) + DIM     + h * 64 + d2];
        Vs[i] = base[(size_t)n * (3 * DIM) + 2 * DIM + h * 64 + d2];
    }
    float qreg[32];
    const float* qrow = base + (size_t)q * (3 * DIM) + h * 64 + half * 32;
#pragma unroll
    for (int j = 0; j < 32; j++) qreg[j] = qrow[j];
    __syncthreads();

#pragma unroll 4
    for (int k = 0; k < 64; k++) {
        float s = 0.f;
#pragma unroll
        for (int j = 0; j < 32; j++) s = fmaf(qreg[j], Ks[k * 64 + half * 32 + j], s);
        scp[half * 4096 + q * 64 + k] = s;
    }
    __syncthreads();

    if (half == 0) {
        float sc[64];
        float mx = -1e30f;
#pragma unroll
        for (int k = 0; k < 64; k++) {
            sc[k] = (scp[q * 64 + k] + scp[4096 + q * 64 + k]) * 0.125f;
            mx = fmaxf(mx, sc[k]);
        }
        float sum = 0.f;
#pragma unroll
        for (int k = 0; k < 64; k++) { sc[k] = expf(sc[k] - mx); sum += sc[k]; }
        float inv = 1.f / sum;
#pragma unroll
        for (int k = 0; k < 64; k++) scp[q * 64 + k] = sc[k] * inv;
    }
    __syncthreads();

    float* orow = g_attout + (size_t)(b * 64 + q) * DIM + h * 64 + half * 32;
#pragma unroll 4
    for (int d2 = 0; d2 < 32; d2++) {
        float o = 0.f;
#pragma unroll
        for (int k = 0; k < 64; k++) o = fmaf(scp[q * 64 + k], Vs[k * 64 + half * 32 + d2], o);
        orow[d2] = f2tf32f(o);
    }
}

// ---------------- streams / events ----------------
#define DSM8B (3 * (256 * 36 + 32 * 136) * 4)   // TM=4,TN=8: 162,816 B
#define DSM4  (3 * (128 * 36 + 32 * 72) * 4)    // TM=2,TN=4
#define DSMA ((4096 + 4096 + 8192) * 4)
struct SfStreams {
    cudaStream_t s1, s2;
    cudaEvent_t e_root, e_pre, e_inits, e_sample, e_wout, e_t2, e_proj, e_outi;
    SfStreams() {
        cudaStreamCreateWithFlags(&s1, cudaStreamNonBlocking);
        cudaStreamCreateWithFlags(&s2, cudaStreamNonBlocking);
        cudaEventCreateWithFlags(&e_root,   cudaEventDisableTiming);
        cudaEventCreateWithFlags(&e_pre,    cudaEventDisableTiming);
        cudaEventCreateWithFlags(&e_inits,  cudaEventDisableTiming);
        cudaEventCreateWithFlags(&e_sample, cudaEventDisableTiming);
        cudaEventCreateWithFlags(&e_wout,   cudaEventDisableTiming);
        cudaEventCreateWithFlags(&e_t2,     cudaEventDisableTiming);
        cudaEventCreateWithFlags(&e_proj,   cudaEventDisableTiming);
        cudaEventCreateWithFlags(&e_outi,   cudaEventDisableTiming);
        cudaFuncSetAttribute((const void*)mma_gemm_t<4, 8>,
                             cudaFuncAttributeMaxDynamicSharedMemorySize, DSM8B);
        cudaFuncSetAttribute((const void*)mma_gemm_t<2, 4>,
                             cudaFuncAttributeMaxDynamicSharedMemorySize, DSM4);
        cudaFuncSetAttribute(mixmma_k, cudaFuncAttributeMaxDynamicSharedMemorySize,
                             MIX_SMF * 4);
        cudaFuncSetAttribute(attn_k, cudaFuncAttributeMaxDynamicSharedMemorySize, DSMA);
    }
};
static SfStreams g_sf;

// ---------------- launch ----------------
extern "C" void kernel_launch(void* const* d_in, const int* in_sizes, int n_in,
                              void* d_out, int out_size) {
    const float* token_embed = (const float*)d_in[0];
    const float* token_roi   = (const float*)d_in[1];
    const float* img_feat    = (const float*)d_in[2];
    const float* ln_off_g    = (const float*)d_in[3];
    const float* ln_off_b    = (const float*)d_in[4];
    const float* w_off       = (const float*)d_in[5];
    const float* off_bias    = (const float*)d_in[6];
    const float* ln_pg_g     = (const float*)d_in[7];
    const float* ln_pg_b     = (const float*)d_in[8];
    const float* w_pg1       = (const float*)d_in[9];
    const float* b_pg1       = (const float*)d_in[10];
    const float* w_pg2       = (const float*)d_in[11];
    const float* b_pg2       = (const float*)d_in[12];
    const float* m_beta      = (const float*)d_in[13];
    const float* s_beta      = (const float*)d_in[14];
    const float* w_out       = (const float*)d_in[15];
    const float* b_out       = (const float*)d_in[16];
    const float* ln1_g       = (const float*)d_in[17];
    const float* ln1_b       = (const float*)d_in[18];
    const float* w_qkv       = (const float*)d_in[19];
    const float* b_qkv       = (const float*)d_in[20];
    const float* w_proj      = (const float*)d_in[21];
    const float* b_proj      = (const float*)d_in[22];
    const float* ln2_g       = (const float*)d_in[23];
    const float* ln2_b       = (const float*)d_in[24];
    const float* w_fc1       = (const float*)d_in[25];
    const float* b_fc1       = (const float*)d_in[26];
    const float* w_fc2       = (const float*)d_in[27];
    const float* b_fc2       = (const float*)d_in[28];
    float* out = (float*)d_out;

    void* p;
    cudaGetSymbolAddress(&p, g_hidden);  float* hidden = (float*)p;
    cudaGetSymbolAddress(&p, g_params);  float* params = (float*)p;
    cudaGetSymbolAddress(&p, g_h);       float* hbuf   = (float*)p;
    cudaGetSymbolAddress(&p, g_tok);     float* tok    = (float*)p;
    cudaGetSymbolAddress(&p, g_tok2);    float* tok2   = (float*)p;
    cudaGetSymbolAddress(&p, g_x);       float* xbuf   = (float*)p;
    cudaGetSymbolAddress(&p, g_qkv);     float* qkv    = (float*)p;
    cudaGetSymbolAddress(&p, g_attout);  float* attout = (float*)p;
    cudaGetSymbolAddress(&p, g_ff);      float* ff     = (float*)p;

    const int DSMX = MIX_SMF * 4;
    cudaStream_t s0 = 0, s1 = g_sf.s1, s2 = g_sf.s2;

    // ---- fork ----
    cudaEventRecord(g_sf.e_root, s0);
    cudaStreamWaitEvent(s1, g_sf.e_root, 0);
    cudaStreamWaitEvent(s2, g_sf.e_root, 0);

    // s0: pre_k -> params GEMM (TM=4,TN=8; raw w_pg2)
    pre_k<<<TKN, 128, 0, s0>>>(token_embed, token_roi, ln_off_g, ln_off_b, w_off, off_bias,
                               ln_pg_g, ln_pg_b, w_pg1, b_pg1);
    cudaEventRecord(g_sf.e_pre, s0);
    mma_gemm_t<4, 8><<<dim3((TOTN + 127) / 128, TKN / 256, 1), 256, DSM8B, s0>>>(
        hidden, w_pg2, b_pg2, params, TKN, TOTN, PGN, 1, 0);

    // s1: inits
    init_k<<<(TKN * DIM + 255) / 256, 256, 0, s1>>>(token_embed, b_out, tok, TKN * DIM, DIM);
    init_k<<<(TKN * 3 * DIM + 255) / 256, 256, 0, s1>>>(nullptr, b_qkv, qkv, TKN * 3 * DIM, 3 * DIM);
    cudaEventRecord(g_sf.e_inits, s1);

    // s2: transpose, then sampling
    transpose_k<<<dim3((HGT * WID) / 32, CCH / 32, 8), 256, 0, s2>>>(img_feat);
    cudaStreamWaitEvent(s2, g_sf.e_pre, 0);
    sample_k<<<dim3(PPT, TKN), 64, 0, s2>>>();
    cudaEventRecord(g_sf.e_sample, s2);

    // s0: mixing
    cudaStreamWaitEvent(s0, g_sf.e_sample, 0);
    mixmma_k<<<TKN, 256, DSMX, s0>>>(m_beta, s_beta);

    // s0: w_out GEMM (TM=2,TN=4, splitK16)
    cudaStreamWaitEvent(s0, g_sf.e_inits, 0);
    mma_gemm_t<2, 4><<<dim3(DIM / 64, TKN / 128, 16), 256, DSM4, s0>>>(
        hbuf, w_out, nullptr, tok, TKN, DIM, PPT * CCH, 0, 0);
    cudaEventRecord(g_sf.e_wout, s0);

    // s1: init_tok2 in parallel
    cudaStreamWaitEvent(s1, g_sf.e_wout, 0);
    init_k<<<(TKN * DIM + 255) / 256, 256, 0, s1>>>(tok, b_proj, tok2, TKN * DIM, DIM);
    cudaEventRecord(g_sf.e_t2, s1);

    // s0: LN1 -> qkv -> attention
    ln_k<<<TKN, 128, 0, s0>>>(tok, ln1_g, ln1_b, xbuf);
    mma_gemm_t<2, 4><<<dim3((3 * DIM) / 64, TKN / 128, 4), 256, DSM4, s0>>>(
        xbuf, w_qkv, nullptr, qkv, TKN, 3 * DIM, DIM, 0, 0);
    attn_k<<<dim3(8, 8), 128, DSMA, s0>>>();
    // s0: proj
    cudaStreamWaitEvent(s0, g_sf.e_t2, 0);
    mma_gemm_t<2, 4><<<dim3(DIM / 64, TKN / 128, 8), 256, DSM4, s0>>>(
        attout, w_proj, nullptr, tok2, TKN, DIM, DIM, 0, 0);
    cudaEventRecord(g_sf.e_proj, s0);

    // s2: init_out in parallel
    cudaStreamWaitEvent(s2, g_sf.e_proj, 0);
    init_k<<<(TKN * DIM + 255) / 256, 256, 0, s2>>>(tok2, b_fc2, out, TKN * DIM, DIM);
    cudaEventRecord(g_sf.e_outi, s2);

    // s0: LN2 -> fc1 (fused bias+gelu) -> fc2
    ln_k<<<TKN, 128, 0, s0>>>(tok2, ln2_g, ln2_b, xbuf);
    mma_gemm_t<2, 4><<<dim3((4 * DIM) / 64, TKN / 128, 1), 256, DSM4, s0>>>(
        xbuf, w_fc1, b_fc1, ff, TKN, 4 * DIM, DIM, 0, 1);
    cudaStreamWaitEvent(s0, g_sf.e_outi, 0);
    mma_gemm_t<2, 4><<<dim3(DIM / 64, TKN / 128, 16), 256, DSM4, s0>>>(
        ff, w_fc2, nullptr, out, TKN, DIM, 4 * DIM, 0, 0);
}

// round 15
// speedup vs baseline: 1.0341x; 1.0341x over previous
#include <cuda_runtime.h>
#include <math.h>
#include <stdint.h>

// ---------------- constants ----------------
#define TKN 512
#define DIM 512
#define CCH 256
#define HGT 128
#define WID 128
#define PPT 36
#define PGN 128
#define TOTN 66832
#define CC2 65536

// ---------------- scratch ----------------
__device__ float g_imgT[8 * HGT * WID * CCH];
__device__ float g_hidden[TKN * PGN];
__device__ float g_grid[TKN * PPT * 2];
__device__ float g_params[(size_t)TKN * TOTN];
__device__ float g_sampled[TKN * PPT * CCH];
__device__ float g_h[TKN * PPT * CCH];
__device__ float g_tok[TKN * DIM];
__device__ float g_tok2[TKN * DIM];
__device__ float g_x[TKN * DIM];
__device__ float g_qkv[TKN * 3 * DIM];
__device__ float g_attout[TKN * DIM];
__device__ float g_ff[TKN * 4 * DIM];

__device__ __forceinline__ float gelu_f(float x) {
    return 0.5f * x * (1.0f + erff(x * 0.70710678118654752440f));
}
__device__ __forceinline__ float f2tf32f(float x) {
    uint32_t r;
    asm("cvt.rna.tf32.f32 %0, %1;" : "=r"(r) : "f"(x));
    return __uint_as_float(r);
}
__device__ __forceinline__ void red2f(float* p, float a, float b) {
    asm volatile("red.global.add.v2.f32 [%0], {%1, %2};"
                 :: "l"(p), "f"(a), "f"(b) : "memory");
}

// ---------------- img transpose ----------------
__global__ void transpose_k(const float* __restrict__ in) {
    __shared__ float tile[32][33];
    int b = blockIdx.z;
    int s0 = blockIdx.x * 32;
    int c0 = blockIdx.y * 32;
    const float* ib = in + (size_t)b * CCH * HGT * WID;
    float* ob = g_imgT + (size_t)b * HGT * WID * CCH;
    int tid = threadIdx.x;
    {
        int c = tid >> 3, s4 = tid & 7;
        float4 v = *(const float4*)(ib + (size_t)(c0 + c) * (HGT * WID) + s0 + 4 * s4);
        tile[4 * s4 + 0][c] = v.x;
        tile[4 * s4 + 1][c] = v.y;
        tile[4 * s4 + 2][c] = v.z;
        tile[4 * s4 + 3][c] = v.w;
    }
    __syncthreads();
    {
        int g = tid & 7, s = tid >> 3;
        float4 v;
        v.x = tile[s][4 * g + 0];
        v.y = tile[s][4 * g + 1];
        v.z = tile[s][4 * g + 2];
        v.w = tile[s][4 * g + 3];
        *(float4*)(ob + (size_t)(s0 + s) * CCH + c0 + 4 * g) = v;
    }
}

// ---------------- per-token pre ----------------
__global__ void pre_k(const float* __restrict__ x, const float* __restrict__ roi,
                      const float* __restrict__ g_off, const float* __restrict__ b_off,
                      const float* __restrict__ w_off, const float* __restrict__ off_bias,
                      const float* __restrict__ g_pg, const float* __restrict__ b_pg,
                      const float* __restrict__ w_pg1, const float* __restrict__ b_pg1) {
    int t = blockIdx.x;
    int tid = threadIdx.x;
    __shared__ float xoff[DIM], xpg[DIM], offs[72];
    __shared__ float rs[4], rs2[4], stats[4];

    const float* xr = x + (size_t)t * DIM;
    float v[4], s = 0.f, s2 = 0.f;
#pragma unroll
    for (int i = 0; i < 4; i++) { v[i] = xr[tid + 128 * i]; s += v[i]; s2 += v[i] * v[i]; }
#pragma unroll
    for (int o = 16; o; o >>= 1) {
        s  += __shfl_down_sync(0xffffffffu, s,  o);
        s2 += __shfl_down_sync(0xffffffffu, s2, o);
    }
    if ((tid & 31) == 0) { rs[tid >> 5] = s; rs2[tid >> 5] = s2; }
    __syncthreads();
    float ts = rs[0] + rs[1] + rs[2] + rs[3];
    float ts2 = rs2[0] + rs2[1] + rs2[2] + rs2[3];
    float mean = ts * (1.f / DIM);
    float var = ts2 * (1.f / DIM) - mean * mean;
    float rstd = rsqrtf(var + 1e-5f);
#pragma unroll
    for (int i = 0; i < 4; i++) {
        int k = tid + 128 * i;
        float xn = (v[i] - mean) * rstd;
        xoff[k] = xn * g_off[k] + b_off[k];
        xpg[k]  = xn * g_pg[k]  + b_pg[k];
    }
    __syncthreads();

    {
        float h = b_pg1[tid];
        for (int k = 0; k < DIM; k++) h = fmaf(xpg[k], w_pg1[k * PGN + tid], h);
        g_hidden[t * PGN + tid] = f2tf32f(h);
    }
    if (tid < 72) {
        float o = off_bias[tid];
        for (int k = 0; k < DIM; k++) o = fmaf(xoff[k], w_off[k * 72 + tid], o);
        offs[tid] = o;
    }
    __syncthreads();
    if (tid < 2) {
        float mu = 0.f;
        for (int p = 0; p < PPT; p++) mu += offs[p * 2 + tid];
        mu *= (1.f / PPT);
        float vv = 0.f;
        for (int p = 0; p < PPT; p++) { float d = offs[p * 2 + tid] - mu; vv += d * d; }
        vv *= (1.f / (PPT - 1));
        stats[tid * 2] = mu;
        stats[tid * 2 + 1] = sqrtf(vv) + 1e-5f;
    }
    __syncthreads();
    if (tid < 72) {
        int coord = tid & 1, p = tid >> 1;
        float mu = stats[coord * 2], sd = stats[coord * 2 + 1];
        float on = (offs[tid] - mu) / (3.f * sd);
        float tl = roi[t * 4 + coord], br = roi[t * 4 + 2 + coord];
        float xy = 0.5f * (tl + br), wh = br - tl;
        float pt = xy + on * wh;
        g_grid[(t * PPT + p) * 2 + coord] = pt * 2.f - 1.f;
    }
}

// ---------------- bilinear grid sample ----------------
__global__ void sample_k() {
    int p = blockIdx.x, t = blockIdx.y;
    int c4 = threadIdx.x << 2;
    int b = t >> 6;
    float gx = g_grid[(t * PPT + p) * 2 + 0];
    float gy = g_grid[(t * PPT + p) * 2 + 1];
    float x = ((gx + 1.f) * WID - 1.f) * 0.5f;
    float y = ((gy + 1.f) * HGT - 1.f) * 0.5f;
    float x0f = floorf(x), y0f = floorf(y);
    float wx = x - x0f, wy = y - y0f;
    int x0 = min(max((int)x0f, 0), WID - 1);
    int x1 = min(max((int)x0f + 1, 0), WID - 1);
    int y0 = min(max((int)y0f, 0), HGT - 1);
    int y1 = min(max((int)y0f + 1, 0), HGT - 1);
    const float* ib = g_imgT + (size_t)b * HGT * WID * CCH;
    float4 v00 = *(const float4*)(ib + (size_t)(y0 * WID + x0) * CCH + c4);
    float4 v01 = *(const float4*)(ib + (size_t)(y0 * WID + x1) * CCH + c4);
    float4 v10 = *(const float4*)(ib + (size_t)(y1 * WID + x0) * CCH + c4);
    float4 v11 = *(const float4*)(ib + (size_t)(y1 * WID + x1) * CCH + c4);
    float w00 = (1.f - wx) * (1.f - wy), w01 = wx * (1.f - wy);
    float w10 = (1.f - wx) * wy,         w11 = wx * wy;
    float4 o;
    o.x = v00.x * w00 + v01.x * w01 + v10.x * w10 + v11.x * w11;
    o.y = v00.y * w00 + v01.y * w01 + v10.y * w10 + v11.y * w11;
    o.z = v00.z * w00 + v01.z * w01 + v10.z * w10 + v11.z * w11;
    o.w = v00.w * w00 + v01.w * w01 + v10.w * w10 + v11.w * w11;
    *(float4*)(g_sampled + ((size_t)t * PPT + p) * CCH + c4) = o;
}

// ---------------- cp.async helpers ----------------
__device__ __forceinline__ void cpa16(uint32_t dst, const void* src, bool pred) {
    int sz = pred ? 16 : 0;
    asm volatile("cp.async.cg.shared.global [%0], [%1], 16, %2;"
                 :: "r"(dst), "l"(src), "r"(sz));
}
__device__ __forceinline__ void cpa_commit() {
    asm volatile("cp.async.commit_group;");
}
__device__ __forceinline__ uint32_t smem_u32(const void* p) {
    uint32_t a;
    asm("{ .reg .u64 t; cvta.to.shared.u64 t, %1; cvt.u32.u64 %0, t; }" : "=r"(a) : "l"(p));
    return a;
}

// ---------------- templated tf32 GEMM: 128-row x TN*16-col tile ----------------
// 3-buffer cp.async pipeline, 1 barrier/ktile. Raw fp32 B (HW tf32 truncation).
#define ASZ 4608
template <int TN>
__global__ void __launch_bounds__(256)
mma_gemm_t(const float* __restrict__ A, const float* __restrict__ Bm,
           const float* __restrict__ bias, float* __restrict__ C,
           int M, int N, int K, int rnd, int act) {
    constexpr int BN   = TN * 16;
    constexpr int BSTR = BN + 8;
    constexpr int BSZf = 32 * BSTR;
    constexpr int STGf = ASZ + BSZf;
    constexpr int BIT  = BN / 32;
    constexpr int BQ   = BN / 4;

    extern __shared__ float smf[];
    uint32_t sbase = smem_u32(smf);

    int tid = threadIdx.x;
    int warp = tid >> 5, lane = tid & 31;
    int wr = (warp >> 1) * 32;
    int wc = (warp & 1) * (TN * 8);
    int bR = blockIdx.y * 128, bC = blockIdx.x * BN;
    int nz = gridDim.z;
    int Kc = K / nz;
    int kbeg = blockIdx.z * Kc;
    int ntiles = Kc >> 5;

    float acc[2][TN][4];
#pragma unroll
    for (int a = 0; a < 2; a++)
#pragma unroll
        for (int b = 0; b < TN; b++)
#pragma unroll
            for (int c = 0; c < 4; c++) acc[a][b][c] = 0.f;

    int ar[4], ac[4];
#pragma unroll
    for (int i = 0; i < 4; i++) {
        int f = tid + (i << 8);
        ar[i] = f >> 3;  ac[i] = (f & 7) << 2;
    }
    int br_[BIT], bc_[BIT];
#pragma unroll
    for (int i = 0; i < BIT; i++) {
        int f = tid + (i << 8);
        br_[i] = f / BQ; bc_[i] = (f % BQ) << 2;
    }

    auto issue = [&](int t, int stage) {
        int k0 = kbeg + (t << 5);
        uint32_t sa = sbase + stage * (STGf * 4);
#pragma unroll
        for (int i = 0; i < 4; i++) {
            cpa16(sa + (ar[i] * 36 + ac[i]) * 4,
                  A + (size_t)(bR + ar[i]) * K + k0 + ac[i], true);
        }
        uint32_t sb = sa + ASZ * 4;
#pragma unroll
        for (int i = 0; i < BIT; i++) {
            int gc = bC + bc_[i];
            cpa16(sb + (br_[i] * BSTR + bc_[i]) * 4,
                  Bm + (size_t)(k0 + br_[i]) * N + gc, gc < N);
        }
        cpa_commit();
    };

    issue(0, 0);
    if (ntiles > 1) issue(1, 1);
    int rd = 0;
    int wrb = 2;
    for (int t = 0; t < ntiles; t++) {
        if (t + 1 < ntiles) {
            asm volatile("cp.async.wait_group 1;");
        } else {
            asm volatile("cp.async.wait_group 0;");
        }
        __syncthreads();
        if (t + 2 < ntiles) {
            issue(t + 2, wrb);
            wrb = (wrb == 2) ? 0 : wrb + 1;
        }
        const uint32_t* As = (const uint32_t*)(smf + rd * STGf);
        const uint32_t* Bs = As + ASZ;
        rd = (rd == 2) ? 0 : rd + 1;
#pragma unroll
        for (int k8 = 0; k8 < 4; k8++) {
            int kk = k8 << 3;
            uint32_t afr[2][4];
#pragma unroll
            for (int tm = 0; tm < 2; tm++) {
                int r = wr + tm * 16 + (lane >> 2);
                int c = kk + (lane & 3);
                afr[tm][0] = As[r * 36 + c];
                afr[tm][1] = As[(r + 8) * 36 + c];
                afr[tm][2] = As[r * 36 + c + 4];
                afr[tm][3] = As[(r + 8) * 36 + c + 4];
            }
#pragma unroll
            for (int tn = 0; tn < TN; tn++) {
                int col = wc + tn * 8 + (lane >> 2);
                uint32_t b0 = Bs[(kk + (lane & 3)) * BSTR + col];
                uint32_t b1 = Bs[(kk + (lane & 3) + 4) * BSTR + col];
#pragma unroll
                for (int tm = 0; tm < 2; tm++) {
                    asm volatile(
                        "mma.sync.aligned.m16n8k8.row.col.f32.tf32.tf32.f32 "
                        "{%0,%1,%2,%3}, {%4,%5,%6,%7}, {%8,%9}, {%0,%1,%2,%3};"
                        : "+f"(acc[tm][tn][0]), "+f"(acc[tm][tn][1]),
                          "+f"(acc[tm][tn][2]), "+f"(acc[tm][tn][3])
                        : "r"(afr[tm][0]), "r"(afr[tm][1]),
                          "r"(afr[tm][2]), "r"(afr[tm][3]),
                          "r"(b0), "r"(b1));
                }
            }
        }
    }

    if (nz == 1) {
#pragma unroll
        for (int tm = 0; tm < 2; tm++) {
            int row = bR + wr + tm * 16 + (lane >> 2);
#pragma unroll
            for (int tn = 0; tn < TN; tn++) {
                int col = bC + wc + tn * 8 + ((lane & 3) << 1);
                if (col >= N) continue;
                float bv0 = 0.f, bv1 = 0.f;
                if (bias) { bv0 = bias[col]; bv1 = bias[col + 1]; }
                float o0 = acc[tm][tn][0] + bv0, o1 = acc[tm][tn][1] + bv1;
                float o2 = acc[tm][tn][2] + bv0, o3 = acc[tm][tn][3] + bv1;
                if (act) {
                    o0 = gelu_f(o0); o1 = gelu_f(o1);
                    o2 = gelu_f(o2); o3 = gelu_f(o3);
                }
                if (rnd | act) {
                    o0 = f2tf32f(o0); o1 = f2tf32f(o1);
                    o2 = f2tf32f(o2); o3 = f2tf32f(o3);
                }
                *(float2*)(&C[(size_t)row * N + col])       = make_float2(o0, o1);
                *(float2*)(&C[(size_t)(row + 8) * N + col]) = make_float2(o2, o3);
            }
        }
    } else {
#pragma unroll
        for (int tm = 0; tm < 2; tm++) {
            int row = bR + wr + tm * 16 + (lane >> 2);
#pragma unroll
            for (int tn = 0; tn < TN; tn++) {
                int col = bC + wc + tn * 8 + ((lane & 3) << 1);
                red2f(&C[(size_t)row * N + col], acc[tm][tn][0], acc[tm][tn][1]);
                red2f(&C[(size_t)(row + 8) * N + col], acc[tm][tn][2], acc[tm][tn][3]);
            }
        }
    }
}

// ---------------- fused early init: tok = resid + b_out ; qkv = b_qkv ----------------
__global__ void init2_k(const float* __restrict__ resid, const float* __restrict__ b_out,
                        const float* __restrict__ b_qkv,
                        float* __restrict__ tok, float* __restrict__ qkv) {
    int i = blockIdx.x * 256 + threadIdx.x;
    if (i < TKN * DIM) {
        tok[i] = resid[i] + b_out[i & (DIM - 1)];
    }
    // qkv region: total TKN*3*DIM = 786432 elements, grid covers both
    int j = i - TKN * DIM;
    if (j >= 0 && j < TKN * 3 * DIM) {
        qkv[j] = b_qkv[j % (3 * DIM)];
    }
}

// ---------------- init ----------------
__global__ void init_k(const float* __restrict__ resid, const float* __restrict__ bias,
                       float* __restrict__ C, int n, int N) {
    int i = blockIdx.x * 256 + threadIdx.x;
    if (i < n) {
        int col = i % N;
        C[i] = (resid ? resid[i] : 0.f) + bias[col];
    }
}

// ---------------- tensor-core per-token mixing ----------------
#define MIX_ASTR 260
#define MIX_BSTR 264
#define MIX_AF (48 * MIX_ASTR)
#define MIX_BF (32 * MIX_BSTR)
#define MIX_SMF (MIX_AF + 2 * MIX_BF + 1296)
__global__ void __launch_bounds__(256)
mixmma_k(const float* __restrict__ mb, const float* __restrict__ sb) {
    extern __shared__ float smf[];
    float* Aa  = smf;
    float* Bb  = smf + MIX_AF;
    float* sms = smf + MIX_AF + 2 * MIX_BF;
    uint32_t sbase = smem_u32(smf);

    int t = blockIdx.x, tid = threadIdx.x;
    int warp = tid >> 5, lane = tid & 31;
    const float* pt = g_params + (size_t)t * TOTN;

    for (int i = tid; i < 12 * MIX_ASTR; i += 256) Aa[36 * MIX_ASTR + i] = 0.f;
    const float4* sp4 = (const float4*)(g_sampled + (size_t)t * (PPT * CCH));
    for (int i = tid; i < PPT * CCH / 4; i += 256) {
        float4 v = sp4[i];
        int r = i >> 6, c = (i & 63) << 2;
        float* d = Aa + r * MIX_ASTR + c;
        d[0] = f2tf32f(v.x); d[1] = f2tf32f(v.y);
        d[2] = f2tf32f(v.z); d[3] = f2tf32f(v.w);
    }
    for (int i = tid; i < PPT * PPT; i += 256) sms[i] = pt[CC2 + i];

    uint32_t bB = sbase + MIX_AF * 4;
    auto issue = [&](int ch, int stg) {
        const float* src = pt + ch * 32 * 256;
        uint32_t dst = bB + stg * (MIX_BF * 4);
#pragma unroll
        for (int i = 0; i < 8; i++) {
            int e = tid + (i << 8);
            int r = e >> 6, c4 = (e & 63) << 2;
            cpa16(dst + (r * MIX_BSTR + c4) * 4, src + r * 256 + c4, true);
        }
        cpa_commit();
    };

    float acc[3][4][4];
#pragma unroll
    for (int a = 0; a < 3; a++)
#pragma unroll
        for (int b = 0; b < 4; b++)
#pragma unroll
            for (int c = 0; c < 4; c++) acc[a][b][c] = 0.f;

    issue(0, 0);
    for (int ch = 0; ch < 8; ch++) {
        if (ch + 1 < 8) {
            issue(ch + 1, (ch + 1) & 1);
            asm volatile("cp.async.wait_group 1;");
        } else {
            asm volatile("cp.async.wait_group 0;");
        }
        __syncthreads();
        const uint32_t* As = (const uint32_t*)Aa;
        const uint32_t* Bs = (const uint32_t*)(Bb + (ch & 1) * MIX_BF);
#pragma unroll
        for (int k8 = 0; k8 < 4; k8++) {
            int kk = (ch << 5) + (k8 << 3);
            int kb = k8 << 3;
            uint32_t afr[3][4];
#pragma unroll
            for (int mt = 0; mt < 3; mt++) {
                int r = mt * 16 + (lane >> 2);
                int c = kk + (lane & 3);
                afr[mt][0] = As[r * MIX_ASTR + c];
                afr[mt][1] = As[(r + 8) * MIX_ASTR + c];
                afr[mt][2] = As[r * MIX_ASTR + c + 4];
                afr[mt][3] = As[(r + 8) * MIX_ASTR + c + 4];
            }
#pragma unroll
            for (int tn = 0; tn < 4; tn++) {
                int col = warp * 32 + tn * 8 + (lane >> 2);
                uint32_t b0 = Bs[(kb + (lane & 3)) * MIX_BSTR + col];
                uint32_t b1 = Bs[(kb + (lane & 3) + 4) * MIX_BSTR + col];
#pragma unroll
                for (int mt = 0; mt < 3; mt++) {
                    asm volatile(
                        "mma.sync.aligned.m16n8k8.row.col.f32.tf32.tf32.f32 "
                        "{%0,%1,%2,%3}, {%4,%5,%6,%7}, {%8,%9}, {%0,%1,%2,%3};"
                        : "+f"(acc[mt][tn][0]), "+f"(acc[mt][tn][1]),
                          "+f"(acc[mt][tn][2]), "+f"(acc[mt][tn][3])
                        : "r"(afr[mt][0]), "r"(afr[mt][1]),
                          "r"(afr[mt][2]), "r"(afr[mt][3]),
                          "r"(b0), "r"(b1));
                }
            }
        }
        __syncthreads();
    }

    float* hsh = Bb;
#pragma unroll
    for (int mt = 0; mt < 3; mt++) {
#pragma unroll
        for (int half = 0; half < 2; half++) {
            int row = mt * 16 + (lane >> 2) + half * 8;
            if (row >= PPT) continue;
#pragma unroll
            for (int tn = 0; tn < 4; tn++) {
                int col = warp * 32 + tn * 8 + ((lane & 3) << 1);
                hsh[row * 260 + col]     = gelu_f(acc[mt][tn][half * 2 + 0] + mb[col]);
                hsh[row * 260 + col + 1] = gelu_f(acc[mt][tn][half * 2 + 1] + mb[col + 1]);
            }
        }
    }
    __syncthreads();

    int d4 = tid & 63;
    int q0 = (tid >> 6) * 9;
    float4 accq[9];
#pragma unroll
    for (int q = 0; q < 9; q++) {
        float s = sb[q0 + q];
        accq[q] = make_float4(s, s, s, s);
    }
    for (int p = 0; p < PPT; p++) {
        float4 hv = *(const float4*)(hsh + p * 260 + 4 * d4);
#pragma unroll
        for (int q = 0; q < 9; q++) {
            float smv = sms[(q0 + q) * PPT + p];
            accq[q].x = fmaf(smv, hv.x, accq[q].x);
            accq[q].y = fmaf(smv, hv.y, accq[q].y);
            accq[q].z = fmaf(smv, hv.z, accq[q].z);
            accq[q].w = fmaf(smv, hv.w, accq[q].w);
        }
    }
    float* ho = g_h + (size_t)t * (PPT * CCH);
#pragma unroll
    for (int q = 0; q < 9; q++) {
        float4 o;
        o.x = f2tf32f(gelu_f(accq[q].x));
        o.y = f2tf32f(gelu_f(accq[q].y));
        o.z = f2tf32f(gelu_f(accq[q].z));
        o.w = f2tf32f(gelu_f(accq[q].w));
        *(float4*)(ho + (q0 + q) * CCH + 4 * d4) = o;
    }
}

// ---------------- layernorm ----------------
__global__ void ln_k(const float* __restrict__ x, const float* __restrict__ g,
                     const float* __restrict__ bb, float* __restrict__ y) {
    int t = blockIdx.x, tid = threadIdx.x;
    __shared__ float rs[4], rs2[4];
    const float* xr = x + (size_t)t * DIM;
    float v[4], s = 0.f, s2 = 0.f;
#pragma unroll
    for (int i = 0; i < 4; i++) { v[i] = xr[tid + 128 * i]; s += v[i]; s2 += v[i] * v[i]; }
#pragma unroll
    for (int o = 16; o; o >>= 1) {
        s  += __shfl_down_sync(0xffffffffu, s,  o);
        s2 += __shfl_down_sync(0xffffffffu, s2, o);
    }
    if ((tid & 31) == 0) { rs[tid >> 5] = s; rs2[tid >> 5] = s2; }
    __syncthreads();
    float ts = rs[0] + rs[1] + rs[2] + rs[3];
    float ts2 = rs2[0] + rs2[1] + rs2[2] + rs2[3];
    float mean = ts * (1.f / DIM);
    float var = ts2 * (1.f / DIM) - mean * mean;
    float rstd = rsqrtf(var + 1e-5f);
#pragma unroll
    for (int i = 0; i < 4; i++) {
        int k = tid + 128 * i;
        y[(size_t)t * DIM + k] = f2tf32f((v[i] - mean) * rstd * g[k] + bb[k]);
    }
}

// ---------------- attention v2 ----------------
__global__ void __launch_bounds__(128) attn_k() {
    extern __shared__ float asm_[];
    float* Ks  = asm_;
    float* Vs  = asm_ + 4096;
    float* scp = asm_ + 8192;

    int b = blockIdx.x, h = blockIdx.y;
    int tid = threadIdx.x;
    int q = tid & 63, half = tid >> 6;
    const float* base = g_qkv + (size_t)b * 64 * (3 * DIM);
    for (int i = tid; i < 64 * 64; i += 128) {
        int n = i >> 6, d2 = i & 63;
        Ks[i] = base[(size_t)n * (3 * DIM) + DIM     + h * 64 + d2];
        Vs[i] = base[(size_t)n * (3 * DIM) + 2 * DIM + h * 64 + d2];
    }
    float qreg[32];
    const float* qrow = base + (size_t)q * (3 * DIM) + h * 64 + half * 32;
#pragma unroll
    for (int j = 0; j < 32; j++) qreg[j] = qrow[j];
    __syncthreads();

#pragma unroll 4
    for (int k = 0; k < 64; k++) {
        float s = 0.f;
#pragma unroll
        for (int j = 0; j < 32; j++) s = fmaf(qreg[j], Ks[k * 64 + half * 32 + j], s);
        scp[half * 4096 + q * 64 + k] = s;
    }
    __syncthreads();

    if (half == 0) {
        float sc[64];
        float mx = -1e30f;
#pragma unroll
        for (int k = 0; k < 64; k++) {
            sc[k] = (scp[q * 64 + k] + scp[4096 + q * 64 + k]) * 0.125f;
            mx = fmaxf(mx, sc[k]);
        }
        float sum = 0.f;
#pragma unroll
        for (int k = 0; k < 64; k++) { sc[k] = expf(sc[k] - mx); sum += sc[k]; }
        float inv = 1.f / sum;
#pragma unroll
        for (int k = 0; k < 64; k++) scp[q * 64 + k] = sc[k] * inv;
    }
    __syncthreads();

    float* orow = g_attout + (size_t)(b * 64 + q) * DIM + h * 64 + half * 32;
#pragma unroll 4
    for (int d2 = 0; d2 < 32; d2++) {
        float o = 0.f;
#pragma unroll
        for (int k = 0; k < 64; k++) o = fmaf(scp[q * 64 + k], Vs[k * 64 + half * 32 + d2], o);
        orow[d2] = f2tf32f(o);
    }
}

// ---------------- streams / events ----------------
#define DSM8 (3 * (ASZ + 32 * 136) * 4)
#define DSM4 (3 * (ASZ + 32 * 72) * 4)
#define DSMA ((4096 + 4096 + 8192) * 4)
struct SfStreams {
    cudaStream_t s1, s2;
    cudaEvent_t e_root, e_pre, e_inits, e_sample, e_wout, e_t2, e_proj, e_outi;
    SfStreams() {
        cudaStreamCreateWithFlags(&s1, cudaStreamNonBlocking);
        cudaStreamCreateWithFlags(&s2, cudaStreamNonBlocking);
        cudaEventCreateWithFlags(&e_root,   cudaEventDisableTiming);
        cudaEventCreateWithFlags(&e_pre,    cudaEventDisableTiming);
        cudaEventCreateWithFlags(&e_inits,  cudaEventDisableTiming);
        cudaEventCreateWithFlags(&e_sample, cudaEventDisableTiming);
        cudaEventCreateWithFlags(&e_wout,   cudaEventDisableTiming);
        cudaEventCreateWithFlags(&e_t2,     cudaEventDisableTiming);
        cudaEventCreateWithFlags(&e_proj,   cudaEventDisableTiming);
        cudaEventCreateWithFlags(&e_outi,   cudaEventDisableTiming);
        cudaFuncSetAttribute(mma_gemm_t<8>, cudaFuncAttributeMaxDynamicSharedMemorySize, DSM8);
        cudaFuncSetAttribute(mma_gemm_t<4>, cudaFuncAttributeMaxDynamicSharedMemorySize, DSM4);
        cudaFuncSetAttribute(mixmma_k, cudaFuncAttributeMaxDynamicSharedMemorySize,
                             MIX_SMF * 4);
        cudaFuncSetAttribute(attn_k, cudaFuncAttributeMaxDynamicSharedMemorySize, DSMA);
    }
};
static SfStreams g_sf;

// ---------------- launch ----------------
extern "C" void kernel_launch(void* const* d_in, const int* in_sizes, int n_in,
                              void* d_out, int out_size) {
    const float* token_embed = (const float*)d_in[0];
    const float* token_roi   = (const float*)d_in[1];
    const float* img_feat    = (const float*)d_in[2];
    const float* ln_off_g    = (const float*)d_in[3];
    const float* ln_off_b    = (const float*)d_in[4];
    const float* w_off       = (const float*)d_in[5];
    const float* off_bias    = (const float*)d_in[6];
    const float* ln_pg_g     = (const float*)d_in[7];
    const float* ln_pg_b     = (const float*)d_in[8];
    const float* w_pg1       = (const float*)d_in[9];
    const float* b_pg1       = (const float*)d_in[10];
    const float* w_pg2       = (const float*)d_in[11];
    const float* b_pg2       = (const float*)d_in[12];
    const float* m_beta      = (const float*)d_in[13];
    const float* s_beta      = (const float*)d_in[14];
    const float* w_out       = (const float*)d_in[15];
    const float* b_out       = (const float*)d_in[16];
    const float* ln1_g       = (const float*)d_in[17];
    const float* ln1_b       = (const float*)d_in[18];
    const float* w_qkv       = (const float*)d_in[19];
    const float* b_qkv       = (const float*)d_in[20];
    const float* w_proj      = (const float*)d_in[21];
    const float* b_proj      = (const float*)d_in[22];
    const float* ln2_g       = (const float*)d_in[23];
    const float* ln2_b       = (const float*)d_in[24];
    const float* w_fc1       = (const float*)d_in[25];
    const float* b_fc1       = (const float*)d_in[26];
    const float* w_fc2       = (const float*)d_in[27];
    const float* b_fc2       = (const float*)d_in[28];
    float* out = (float*)d_out;

    void* p;
    cudaGetSymbolAddress(&p, g_hidden);  float* hidden = (float*)p;
    cudaGetSymbolAddress(&p, g_params);  float* params = (float*)p;
    cudaGetSymbolAddress(&p, g_h);       float* hbuf   = (float*)p;
    cudaGetSymbolAddress(&p, g_tok);     float* tok    = (float*)p;
    cudaGetSymbolAddress(&p, g_tok2);    float* tok2   = (float*)p;
    cudaGetSymbolAddress(&p, g_x);       float* xbuf   = (float*)p;
    cudaGetSymbolAddress(&p, g_qkv);     float* qkv    = (float*)p;
    cudaGetSymbolAddress(&p, g_attout);  float* attout = (float*)p;
    cudaGetSymbolAddress(&p, g_ff);      float* ff     = (float*)p;

    const int DSMX = MIX_SMF * 4;
    cudaStream_t s0 = 0, s1 = g_sf.s1, s2 = g_sf.s2;

    // ---- fork ----
    cudaEventRecord(g_sf.e_root, s0);
    cudaStreamWaitEvent(s1, g_sf.e_root, 0);
    cudaStreamWaitEvent(s2, g_sf.e_root, 0);

    // s0: pre_k -> params GEMM (TN=8; raw w_pg2, HW tf32 truncation)
    pre_k<<<TKN, 128, 0, s0>>>(token_embed, token_roi, ln_off_g, ln_off_b, w_off, off_bias,
                               ln_pg_g, ln_pg_b, w_pg1, b_pg1);
    cudaEventRecord(g_sf.e_pre, s0);
    mma_gemm_t<8><<<dim3((TOTN + 127) / 128, TKN / 128, 1), 256, DSM8, s0>>>(
        hidden, w_pg2, b_pg2, params, TKN, TOTN, PGN, 1, 0);

    // s1: fused init (tok residual+bias, qkv bias) in one launch
    init2_k<<<(TKN * DIM + TKN * 3 * DIM + 255) / 256, 256, 0, s1>>>(
        token_embed, b_out, b_qkv, tok, qkv);
    cudaEventRecord(g_sf.e_inits, s1);

    // s2: transpose, then sampling
    transpose_k<<<dim3((HGT * WID) / 32, CCH / 32, 8), 256, 0, s2>>>(img_feat);
    cudaStreamWaitEvent(s2, g_sf.e_pre, 0);
    sample_k<<<dim3(PPT, TKN), 64, 0, s2>>>();
    cudaEventRecord(g_sf.e_sample, s2);

    // s0: mixing
    cudaStreamWaitEvent(s0, g_sf.e_sample, 0);
    mixmma_k<<<TKN, 256, DSMX, s0>>>(m_beta, s_beta);

    // s0: w_out GEMM (TN=4, splitK16)
    cudaStreamWaitEvent(s0, g_sf.e_inits, 0);
    mma_gemm_t<4><<<dim3(DIM / 64, TKN / 128, 16), 256, DSM4, s0>>>(
        hbuf, w_out, nullptr, tok, TKN, DIM, PPT * CCH, 0, 0);
    cudaEventRecord(g_sf.e_wout, s0);

    // s1: init_tok2 in parallel
    cudaStreamWaitEvent(s1, g_sf.e_wout, 0);
    init_k<<<(TKN * DIM + 255) / 256, 256, 0, s1>>>(tok, b_proj, tok2, TKN * DIM, DIM);
    cudaEventRecord(g_sf.e_t2, s1);

    // s0: LN1 -> qkv -> attention
    ln_k<<<TKN, 128, 0, s0>>>(tok, ln1_g, ln1_b, xbuf);
    mma_gemm_t<4><<<dim3((3 * DIM) / 64, TKN / 128, 4), 256, DSM4, s0>>>(
        xbuf, w_qkv, nullptr, qkv, TKN, 3 * DIM, DIM, 0, 0);
    attn_k<<<dim3(8, 8), 128, DSMA, s0>>>();
    // s0: proj
    cudaStreamWaitEvent(s0, g_sf.e_t2, 0);
    mma_gemm_t<4><<<dim3(DIM / 64, TKN / 128, 8), 256, DSM4, s0>>>(
        attout, w_proj, nullptr, tok2, TKN, DIM, DIM, 0, 0);
    cudaEventRecord(g_sf.e_proj, s0);

    // s2: init_out in parallel
    cudaStreamWaitEvent(s2, g_sf.e_proj, 0);
    init_k<<<(TKN * DIM + 255) / 256, 256, 0, s2>>>(tok2, b_fc2, out, TKN * DIM, DIM);
    cudaEventRecord(g_sf.e_outi, s2);

    // s0: LN2 -> fc1 (fused bias+gelu) -> fc2
    ln_k<<<TKN, 128, 0, s0>>>(tok2, ln2_g, ln2_b, xbuf);
    mma_gemm_t<4><<<dim3((4 * DIM) / 64, TKN / 128, 1), 256, DSM4, s0>>>(
        xbuf, w_fc1, b_fc1, ff, TKN, 4 * DIM, DIM, 0, 1);
    cudaStreamWaitEvent(s0, g_sf.e_outi, 0);
    mma_gemm_t<4><<<dim3(DIM / 64, TKN / 128, 16), 256, DSM4, s0>>>(
        ff, w_fc2, nullptr, out, TKN, DIM, 4 * DIM, 0, 0);
}

// round 16
// speedup vs baseline: 1.1798x; 1.1409x over previous
#include <cuda_runtime.h>
#include <cuda_fp16.h>
#include <math.h>
#include <stdint.h>

// ---------------- constants ----------------
#define TKN 512
#define DIM 512
#define CCH 256
#define HGT 128
#define WID 128
#define PPT 36
#define PGN 128
#define TOTN 66832
#define CC2 65536

// ---------------- scratch ----------------
__device__ float g_imgT[8 * HGT * WID * CCH];
__device__ float g_hidden[TKN * PGN];
__device__ float g_grid[TKN * PPT * 2];
__device__ __half g_params_h[(size_t)TKN * TOTN];
__device__ float g_sampled[TKN * PPT * CCH];
__device__ float g_h[TKN * PPT * CCH];
__device__ float g_tok[TKN * DIM];
__device__ float g_tok2[TKN * DIM];
__device__ float g_x[TKN * DIM];
__device__ float g_qkv[TKN * 3 * DIM];
__device__ float g_attout[TKN * DIM];
__device__ float g_ff[TKN * 4 * DIM];

__device__ __forceinline__ float gelu_f(float x) {
    return 0.5f * x * (1.0f + erff(x * 0.70710678118654752440f));
}
__device__ __forceinline__ float f2tf32f(float x) {
    uint32_t r;
    asm("cvt.rna.tf32.f32 %0, %1;" : "=r"(r) : "f"(x));
    return __uint_as_float(r);
}
__device__ __forceinline__ void red2f(float* p, float a, float b) {
    asm volatile("red.global.add.v2.f32 [%0], {%1, %2};"
                 :: "l"(p), "f"(a), "f"(b) : "memory");
}

// ---------------- img transpose ----------------
__global__ void transpose_k(const float* __restrict__ in) {
    __shared__ float tile[32][33];
    int b = blockIdx.z;
    int s0 = blockIdx.x * 32;
    int c0 = blockIdx.y * 32;
    const float* ib = in + (size_t)b * CCH * HGT * WID;
    float* ob = g_imgT + (size_t)b * HGT * WID * CCH;
    int tid = threadIdx.x;
    {
        int c = tid >> 3, s4 = tid & 7;
        float4 v = *(const float4*)(ib + (size_t)(c0 + c) * (HGT * WID) + s0 + 4 * s4);
        tile[4 * s4 + 0][c] = v.x;
        tile[4 * s4 + 1][c] = v.y;
        tile[4 * s4 + 2][c] = v.z;
        tile[4 * s4 + 3][c] = v.w;
    }
    __syncthreads();
    {
        int g = tid & 7, s = tid >> 3;
        float4 v;
        v.x = tile[s][4 * g + 0];
        v.y = tile[s][4 * g + 1];
        v.z = tile[s][4 * g + 2];
        v.w = tile[s][4 * g + 3];
        *(float4*)(ob + (size_t)(s0 + s) * CCH + c0 + 4 * g) = v;
    }
}

// ---------------- per-token pre ----------------
__global__ void pre_k(const float* __restrict__ x, const float* __restrict__ roi,
                      const float* __restrict__ g_off, const float* __restrict__ b_off,
                      const float* __restrict__ w_off, const float* __restrict__ off_bias,
                      const float* __restrict__ g_pg, const float* __restrict__ b_pg,
                      const float* __restrict__ w_pg1, const float* __restrict__ b_pg1) {
    int t = blockIdx.x;
    int tid = threadIdx.x;
    __shared__ float xoff[DIM], xpg[DIM], offs[72];
    __shared__ float rs[4], rs2[4], stats[4];

    const float* xr = x + (size_t)t * DIM;
    float v[4], s = 0.f, s2 = 0.f;
#pragma unroll
    for (int i = 0; i < 4; i++) { v[i] = xr[tid + 128 * i]; s += v[i]; s2 += v[i] * v[i]; }
#pragma unroll
    for (int o = 16; o; o >>= 1) {
        s  += __shfl_down_sync(0xffffffffu, s,  o);
        s2 += __shfl_down_sync(0xffffffffu, s2, o);
    }
    if ((tid & 31) == 0) { rs[tid >> 5] = s; rs2[tid >> 5] = s2; }
    __syncthreads();
    float ts = rs[0] + rs[1] + rs[2] + rs[3];
    float ts2 = rs2[0] + rs2[1] + rs2[2] + rs2[3];
    float mean = ts * (1.f / DIM);
    float var = ts2 * (1.f / DIM) - mean * mean;
    float rstd = rsqrtf(var + 1e-5f);
#pragma unroll
    for (int i = 0; i < 4; i++) {
        int k = tid + 128 * i;
        float xn = (v[i] - mean) * rstd;
        xoff[k] = xn * g_off[k] + b_off[k];
        xpg[k]  = xn * g_pg[k]  + b_pg[k];
    }
    __syncthreads();

    {
        float h = b_pg1[tid];
        for (int k = 0; k < DIM; k++) h = fmaf(xpg[k], w_pg1[k * PGN + tid], h);
        g_hidden[t * PGN + tid] = f2tf32f(h);
    }
    if (tid < 72) {
        float o = off_bias[tid];
        for (int k = 0; k < DIM; k++) o = fmaf(xoff[k], w_off[k * 72 + tid], o);
        offs[tid] = o;
    }
    __syncthreads();
    if (tid < 2) {
        float mu = 0.f;
        for (int p = 0; p < PPT; p++) mu += offs[p * 2 + tid];
        mu *= (1.f / PPT);
        float vv = 0.f;
        for (int p = 0; p < PPT; p++) { float d = offs[p * 2 + tid] - mu; vv += d * d; }
        vv *= (1.f / (PPT - 1));
        stats[tid * 2] = mu;
        stats[tid * 2 + 1] = sqrtf(vv) + 1e-5f;
    }
    __syncthreads();
    if (tid < 72) {
        int coord = tid & 1, p = tid >> 1;
        float mu = stats[coord * 2], sd = stats[coord * 2 + 1];
        float on = (offs[tid] - mu) / (3.f * sd);
        float tl = roi[t * 4 + coord], br = roi[t * 4 + 2 + coord];
        float xy = 0.5f * (tl + br), wh = br - tl;
        float pt = xy + on * wh;
        g_grid[(t * PPT + p) * 2 + coord] = pt * 2.f - 1.f;
    }
}

// ---------------- bilinear grid sample ----------------
__global__ void sample_k() {
    int p = blockIdx.x, t = blockIdx.y;
    int c4 = threadIdx.x << 2;
    int b = t >> 6;
    float gx = g_grid[(t * PPT + p) * 2 + 0];
    float gy = g_grid[(t * PPT + p) * 2 + 1];
    float x = ((gx + 1.f) * WID - 1.f) * 0.5f;
    float y = ((gy + 1.f) * HGT - 1.f) * 0.5f;
    float x0f = floorf(x), y0f = floorf(y);
    float wx = x - x0f, wy = y - y0f;
    int x0 = min(max((int)x0f, 0), WID - 1);
    int x1 = min(max((int)x0f + 1, 0), WID - 1);
    int y0 = min(max((int)y0f, 0), HGT - 1);
    int y1 = min(max((int)y0f + 1, 0), HGT - 1);
    const float* ib = g_imgT + (size_t)b * HGT * WID * CCH;
    float4 v00 = *(const float4*)(ib + (size_t)(y0 * WID + x0) * CCH + c4);
    float4 v01 = *(const float4*)(ib + (size_t)(y0 * WID + x1) * CCH + c4);
    float4 v10 = *(const float4*)(ib + (size_t)(y1 * WID + x0) * CCH + c4);
    float4 v11 = *(const float4*)(ib + (size_t)(y1 * WID + x1) * CCH + c4);
    float w00 = (1.f - wx) * (1.f - wy), w01 = wx * (1.f - wy);
    float w10 = (1.f - wx) * wy,         w11 = wx * wy;
    float4 o;
    o.x = v00.x * w00 + v01.x * w01 + v10.x * w10 + v11.x * w11;
    o.y = v00.y * w00 + v01.y * w01 + v10.y * w10 + v11.y * w11;
    o.z = v00.z * w00 + v01.z * w01 + v10.z * w10 + v11.z * w11;
    o.w = v00.w * w00 + v01.w * w01 + v10.w * w10 + v11.w * w11;
    *(float4*)(g_sampled + ((size_t)t * PPT + p) * CCH + c4) = o;
}

// ---------------- cp.async helpers ----------------
__device__ __forceinline__ void cpa16(uint32_t dst, const void* src, bool pred) {
    int sz = pred ? 16 : 0;
    asm volatile("cp.async.cg.shared.global [%0], [%1], 16, %2;"
                 :: "r"(dst), "l"(src), "r"(sz));
}
__device__ __forceinline__ void cpa_commit() {
    asm volatile("cp.async.commit_group;");
}
__device__ __forceinline__ uint32_t smem_u32(const void* p) {
    uint32_t a;
    asm("{ .reg .u64 t; cvta.to.shared.u64 t, %1; cvt.u32.u64 %0, t; }" : "=r"(a) : "l"(p));
    return a;
}

// ---------------- templated tf32 GEMM (optional fp16 output C16) ----------------
#define ASZ 4608
template <int TN>
__global__ void __launch_bounds__(256)
mma_gemm_t(const float* __restrict__ A, const float* __restrict__ Bm,
           const float* __restrict__ bias, float* __restrict__ C,
           __half* __restrict__ C16,
           int M, int N, int K, int rnd, int act) {
    constexpr int BN   = TN * 16;
    constexpr int BSTR = BN + 8;
    constexpr int BSZf = 32 * BSTR;
    constexpr int STGf = ASZ + BSZf;
    constexpr int BIT  = BN / 32;
    constexpr int BQ   = BN / 4;

    extern __shared__ float smf[];
    uint32_t sbase = smem_u32(smf);

    int tid = threadIdx.x;
    int warp = tid >> 5, lane = tid & 31;
    int wr = (warp >> 1) * 32;
    int wc = (warp & 1) * (TN * 8);
    int bR = blockIdx.y * 128, bC = blockIdx.x * BN;
    int nz = gridDim.z;
    int Kc = K / nz;
    int kbeg = blockIdx.z * Kc;
    int ntiles = Kc >> 5;

    float acc[2][TN][4];
#pragma unroll
    for (int a = 0; a < 2; a++)
#pragma unroll
        for (int b = 0; b < TN; b++)
#pragma unroll
            for (int c = 0; c < 4; c++) acc[a][b][c] = 0.f;

    int ar[4], ac[4];
#pragma unroll
    for (int i = 0; i < 4; i++) {
        int f = tid + (i << 8);
        ar[i] = f >> 3;  ac[i] = (f & 7) << 2;
    }
    int br_[BIT], bc_[BIT];
#pragma unroll
    for (int i = 0; i < BIT; i++) {
        int f = tid + (i << 8);
        br_[i] = f / BQ; bc_[i] = (f % BQ) << 2;
    }

    auto issue = [&](int t, int stage) {
        int k0 = kbeg + (t << 5);
        uint32_t sa = sbase + stage * (STGf * 4);
#pragma unroll
        for (int i = 0; i < 4; i++) {
            cpa16(sa + (ar[i] * 36 + ac[i]) * 4,
                  A + (size_t)(bR + ar[i]) * K + k0 + ac[i], true);
        }
        uint32_t sb = sa + ASZ * 4;
#pragma unroll
        for (int i = 0; i < BIT; i++) {
            int gc = bC + bc_[i];
            cpa16(sb + (br_[i] * BSTR + bc_[i]) * 4,
                  Bm + (size_t)(k0 + br_[i]) * N + gc, gc < N);
        }
        cpa_commit();
    };

    issue(0, 0);
    if (ntiles > 1) issue(1, 1);
    int rd = 0;
    int wrb = 2;
    for (int t = 0; t < ntiles; t++) {
        if (t + 1 < ntiles) {
            asm volatile("cp.async.wait_group 1;");
        } else {
            asm volatile("cp.async.wait_group 0;");
        }
        __syncthreads();
        if (t + 2 < ntiles) {
            issue(t + 2, wrb);
            wrb = (wrb == 2) ? 0 : wrb + 1;
        }
        const uint32_t* As = (const uint32_t*)(smf + rd * STGf);
        const uint32_t* Bs = As + ASZ;
        rd = (rd == 2) ? 0 : rd + 1;
#pragma unroll
        for (int k8 = 0; k8 < 4; k8++) {
            int kk = k8 << 3;
            uint32_t afr[2][4];
#pragma unroll
            for (int tm = 0; tm < 2; tm++) {
                int r = wr + tm * 16 + (lane >> 2);
                int c = kk + (lane & 3);
                afr[tm][0] = As[r * 36 + c];
                afr[tm][1] = As[(r + 8) * 36 + c];
                afr[tm][2] = As[r * 36 + c + 4];
                afr[tm][3] = As[(r + 8) * 36 + c + 4];
            }
#pragma unroll
            for (int tn = 0; tn < TN; tn++) {
                int col = wc + tn * 8 + (lane >> 2);
                uint32_t b0 = Bs[(kk + (lane & 3)) * BSTR + col];
                uint32_t b1 = Bs[(kk + (lane & 3) + 4) * BSTR + col];
#pragma unroll
                for (int tm = 0; tm < 2; tm++) {
                    asm volatile(
                        "mma.sync.aligned.m16n8k8.row.col.f32.tf32.tf32.f32 "
                        "{%0,%1,%2,%3}, {%4,%5,%6,%7}, {%8,%9}, {%0,%1,%2,%3};"
                        : "+f"(acc[tm][tn][0]), "+f"(acc[tm][tn][1]),
                          "+f"(acc[tm][tn][2]), "+f"(acc[tm][tn][3])
                        : "r"(afr[tm][0]), "r"(afr[tm][1]),
                          "r"(afr[tm][2]), "r"(afr[tm][3]),
                          "r"(b0), "r"(b1));
                }
            }
        }
    }

    if (nz == 1) {
#pragma unroll
        for (int tm = 0; tm < 2; tm++) {
            int row = bR + wr + tm * 16 + (lane >> 2);
#pragma unroll
            for (int tn = 0; tn < TN; tn++) {
                int col = bC + wc + tn * 8 + ((lane & 3) << 1);
                if (col >= N) continue;
                float bv0 = 0.f, bv1 = 0.f;
                if (bias) { bv0 = bias[col]; bv1 = bias[col + 1]; }
                float o0 = acc[tm][tn][0] + bv0, o1 = acc[tm][tn][1] + bv1;
                float o2 = acc[tm][tn][2] + bv0, o3 = acc[tm][tn][3] + bv1;
                if (C16) {
                    *(__half2*)(C16 + (size_t)row * N + col) = __floats2half2_rn(o0, o1);
                    *(__half2*)(C16 + (size_t)(row + 8) * N + col) = __floats2half2_rn(o2, o3);
                } else {
                    if (act) {
                        o0 = gelu_f(o0); o1 = gelu_f(o1);
                        o2 = gelu_f(o2); o3 = gelu_f(o3);
                    }
                    if (rnd | act) {
                        o0 = f2tf32f(o0); o1 = f2tf32f(o1);
                        o2 = f2tf32f(o2); o3 = f2tf32f(o3);
                    }
                    *(float2*)(&C[(size_t)row * N + col])       = make_float2(o0, o1);
                    *(float2*)(&C[(size_t)(row + 8) * N + col]) = make_float2(o2, o3);
                }
            }
        }
    } else {
#pragma unroll
        for (int tm = 0; tm < 2; tm++) {
            int row = bR + wr + tm * 16 + (lane >> 2);
#pragma unroll
            for (int tn = 0; tn < TN; tn++) {
                int col = bC + wc + tn * 8 + ((lane & 3) << 1);
                red2f(&C[(size_t)row * N + col], acc[tm][tn][0], acc[tm][tn][1]);
                red2f(&C[(size_t)(row + 8) * N + col], acc[tm][tn][2], acc[tm][tn][3]);
            }
        }
    }
}

// ---------------- fused early init ----------------
__global__ void init2_k(const float* __restrict__ resid, const float* __restrict__ b_out,
                        const float* __restrict__ b_qkv,
                        float* __restrict__ tok, float* __restrict__ qkv) {
    int i = blockIdx.x * 256 + threadIdx.x;
    if (i < TKN * DIM) {
        tok[i] = resid[i] + b_out[i & (DIM - 1)];
    }
    int j = i - TKN * DIM;
    if (j >= 0 && j < TKN * 3 * DIM) {
        qkv[j] = b_qkv[j % (3 * DIM)];
    }
}

__global__ void init_k(const float* __restrict__ resid, const float* __restrict__ bias,
                       float* __restrict__ C, int n, int N) {
    int i = blockIdx.x * 256 + threadIdx.x;
    if (i < n) {
        int col = i % N;
        C[i] = (resid ? resid[i] : 0.f) + bias[col];
    }
}

// ---------------- fp16 tensor-core per-token mixing ----------------
// A = sampled (fp16, 48x264 halves, rows 36+ zero), B = cm streamed fp16,
// mma.m16n8k16 f16 -> f32. hsh overlays A/B after phase 1.
#define MXH_ABYTES (48 * 264 * 2)                 // 25344
#define MXH_BSTAGE (32 * 264 * 2)                 // 16896
#define MXH_SMSOFF (MXH_ABYTES + 2 * MXH_BSTAGE)  // 59136
#define MXH_TOTAL  (MXH_SMSOFF + 1296 * 4)        // 64320
__global__ void __launch_bounds__(256)
mixmma_k(const float* __restrict__ mb, const float* __restrict__ sb) {
    extern __shared__ __align__(16) char smx[];
    __half* Ah  = (__half*)smx;
    float*  sms = (float*)(smx + MXH_SMSOFF);
    float*  hsh = (float*)smx;                    // overlay after phase 1
    uint32_t sbase = smem_u32(smx);

    int t = blockIdx.x, tid = threadIdx.x;
    int warp = tid >> 5, lane = tid & 31;
    const __half* ph = g_params_h + (size_t)t * TOTN;

    // stage A (sampled -> fp16), rows 0..35
    const float* sp = g_sampled + (size_t)t * (PPT * CCH);
    for (int i = tid; i < PPT * CCH / 2; i += 256) {
        int r = i >> 7, c2 = (i & 127) << 1;
        float2 v = *(const float2*)(sp + r * 256 + c2);
        *(__half2*)(Ah + r * 264 + c2) = __floats2half2_rn(v.x, v.y);
    }
    // zero pad rows 36..47
    for (int i = tid; i < 12 * 264 / 2; i += 256)
        ((uint32_t*)(Ah + 36 * 264))[i] = 0u;
    // stage sm (fp16 -> fp32)
    for (int i = tid; i < PPT * PPT; i += 256)
        sms[i] = __half2float(ph[CC2 + i]);

    auto issue = [&](int ch, int stg) {
        const __half* src = ph + ch * 8192;       // 32 rows x 256 halves
        uint32_t dst = sbase + MXH_ABYTES + stg * MXH_BSTAGE;
#pragma unroll
        for (int i = 0; i < 4; i++) {
            int e = tid + (i << 8);               // 0..1023
            int r = e >> 5, c8 = (e & 31) << 3;   // 8 halves = 16B
            cpa16(dst + (r * 264 + c8) * 2, src + r * 256 + c8, true);
        }
        cpa_commit();
    };

    float acc[3][4][4];
#pragma unroll
    for (int a = 0; a < 3; a++)
#pragma unroll
        for (int b = 0; b < 4; b++)
#pragma unroll
            for (int c = 0; c < 4; c++) acc[a][b][c] = 0.f;

    int g = lane >> 2, tt = lane & 3;
    issue(0, 0);
    for (int ch = 0; ch < 8; ch++) {
        if (ch + 1 < 8) {
            issue(ch + 1, (ch + 1) & 1);
            asm volatile("cp.async.wait_group 1;");
        } else {
            asm volatile("cp.async.wait_group 0;");
        }
        __syncthreads();
        uint32_t bbase = sbase + MXH_ABYTES + (ch & 1) * MXH_BSTAGE;
#pragma unroll
        for (int ks = 0; ks < 2; ks++) {
            int c0 = (ch << 5) + (ks << 4) + (tt << 1);
            uint32_t afr[3][4];
#pragma unroll
            for (int mt = 0; mt < 3; mt++) {
                const __half* ap = Ah + (mt * 16 + g) * 264 + c0;
                afr[mt][0] = *(const uint32_t*)ap;
                afr[mt][1] = *(const uint32_t*)(ap + 8 * 264);
                afr[mt][2] = *(const uint32_t*)(ap + 8);
                afr[mt][3] = *(const uint32_t*)(ap + 8 * 264 + 8);
            }
#pragma unroll
            for (int tn = 0; tn < 4; tn++) {
                int n0 = warp * 32 + tn * 8;
                uint32_t baddr = bbase + (((ks << 4) + (lane & 15)) * 264 + n0) * 2;
                uint32_t b0, b1;
                asm volatile(
                    "ldmatrix.sync.aligned.m8n8.x2.trans.shared.b16 {%0,%1}, [%2];"
                    : "=r"(b0), "=r"(b1) : "r"(baddr));
#pragma unroll
                for (int mt = 0; mt < 3; mt++) {
                    asm volatile(
                        "mma.sync.aligned.m16n8k16.row.col.f32.f16.f16.f32 "
                        "{%0,%1,%2,%3}, {%4,%5,%6,%7}, {%8,%9}, {%0,%1,%2,%3};"
                        : "+f"(acc[mt][tn][0]), "+f"(acc[mt][tn][1]),
                          "+f"(acc[mt][tn][2]), "+f"(acc[mt][tn][3])
                        : "r"(afr[mt][0]), "r"(afr[mt][1]),
                          "r"(afr[mt][2]), "r"(afr[mt][3]),
                          "r"(b0), "r"(b1));
                }
            }
        }
        __syncthreads();
    }

    // h = gelu(acc + m_beta) -> hsh (overlay), rows 0..35, stride 260
#pragma unroll
    for (int mt = 0; mt < 3; mt++) {
#pragma unroll
        for (int half = 0; half < 2; half++) {
            int row = mt * 16 + g + half * 8;
            if (row >= PPT) continue;
#pragma unroll
            for (int tn = 0; tn < 4; tn++) {
                int col = warp * 32 + tn * 8 + (tt << 1);
                hsh[row * 260 + col]     = gelu_f(acc[mt][tn][half * 2 + 0] + mb[col]);
                hsh[row * 260 + col + 1] = gelu_f(acc[mt][tn][half * 2 + 1] + mb[col + 1]);
            }
        }
    }
    __syncthreads();

    // phase 2: out = gelu(sm @ h + s_beta)
    int d4 = tid & 63;
    int q0 = (tid >> 6) * 9;
    float4 accq[9];
#pragma unroll
    for (int q = 0; q < 9; q++) {
        float s = sb[q0 + q];
        accq[q] = make_float4(s, s, s, s);
    }
    for (int p = 0; p < PPT; p++) {
        float4 hv = *(const float4*)(hsh + p * 260 + 4 * d4);
#pragma unroll
        for (int q = 0; q < 9; q++) {
            float smv = sms[(q0 + q) * PPT + p];
            accq[q].x = fmaf(smv, hv.x, accq[q].x);
            accq[q].y = fmaf(smv, hv.y, accq[q].y);
            accq[q].z = fmaf(smv, hv.z, accq[q].z);
            accq[q].w = fmaf(smv, hv.w, accq[q].w);
        }
    }
    float* ho = g_h + (size_t)t * (PPT * CCH);
#pragma unroll
    for (int q = 0; q < 9; q++) {
        float4 o;
        o.x = f2tf32f(gelu_f(accq[q].x));
        o.y = f2tf32f(gelu_f(accq[q].y));
        o.z = f2tf32f(gelu_f(accq[q].z));
        o.w = f2tf32f(gelu_f(accq[q].w));
        *(float4*)(ho + (q0 + q) * CCH + 4 * d4) = o;
    }
}

// ---------------- layernorm ----------------
__global__ void ln_k(const float* __restrict__ x, const float* __restrict__ g,
                     const float* __restrict__ bb, float* __restrict__ y) {
    int t = blockIdx.x, tid = threadIdx.x;
    __shared__ float rs[4], rs2[4];
    const float* xr = x + (size_t)t * DIM;
    float v[4], s = 0.f, s2 = 0.f;
#pragma unroll
    for (int i = 0; i < 4; i++) { v[i] = xr[tid + 128 * i]; s += v[i]; s2 += v[i] * v[i]; }
#pragma unroll
    for (int o = 16; o; o >>= 1) {
        s  += __shfl_down_sync(0xffffffffu, s,  o);
        s2 += __shfl_down_sync(0xffffffffu, s2, o);
    }
    if ((tid & 31) == 0) { rs[tid >> 5] = s; rs2[tid >> 5] = s2; }
    __syncthreads();
    float ts = rs[0] + rs[1] + rs[2] + rs[3];
    float ts2 = rs2[0] + rs2[1] + rs2[2] + rs2[3];
    float mean = ts * (1.f / DIM);
    float var = ts2 * (1.f / DIM) - mean * mean;
    float rstd = rsqrtf(var + 1e-5f);
#pragma unroll
    for (int i = 0; i < 4; i++) {
        int k = tid + 128 * i;
        y[(size_t)t * DIM + k] = f2tf32f((v[i] - mean) * rstd * g[k] + bb[k]);
    }
}

// ---------------- attention v2 ----------------
__global__ void __launch_bounds__(128) attn_k() {
    extern __shared__ float asm_[];
    float* Ks  = asm_;
    float* Vs  = asm_ + 4096;
    float* scp = asm_ + 8192;

    int b = blockIdx.x, h = blockIdx.y;
    int tid = threadIdx.x;
    int q = tid & 63, half = tid >> 6;
    const float* base = g_qkv + (size_t)b * 64 * (3 * DIM);
    for (int i = tid; i < 64 * 64; i += 128) {
        int n = i >> 6, d2 = i & 63;
        Ks[i] = base[(size_t)n * (3 * DIM) + DIM     + h * 64 + d2];
        Vs[i] = base[(size_t)n * (3 * DIM) + 2 * DIM + h * 64 + d2];
    }
    float qreg[32];
    const float* qrow = base + (size_t)q * (3 * DIM) + h * 64 + half * 32;
#pragma unroll
    for (int j = 0; j < 32; j++) qreg[j] = qrow[j];
    __syncthreads();

#pragma unroll 4
    for (int k = 0; k < 64; k++) {
        float s = 0.f;
#pragma unroll
        for (int j = 0; j < 32; j++) s = fmaf(qreg[j], Ks[k * 64 + half * 32 + j], s);
        scp[half * 4096 + q * 64 + k] = s;
    }
    __syncthreads();

    if (half == 0) {
        float sc[64];
        float mx = -1e30f;
#pragma unroll
        for (int k = 0; k < 64; k++) {
            sc[k] = (scp[q * 64 + k] + scp[4096 + q * 64 + k]) * 0.125f;
            mx = fmaxf(mx, sc[k]);
        }
        float sum = 0.f;
#pragma unroll
        for (int k = 0; k < 64; k++) { sc[k] = expf(sc[k] - mx); sum += sc[k]; }
        float inv = 1.f / sum;
#pragma unroll
        for (int k = 0; k < 64; k++) scp[q * 64 + k] = sc[k] * inv;
    }
    __syncthreads();

    float* orow = g_attout + (size_t)(b * 64 + q) * DIM + h * 64 + half * 32;
#pragma unroll 4
    for (int d2 = 0; d2 < 32; d2++) {
        float o = 0.f;
#pragma unroll
        for (int k = 0; k < 64; k++) o = fmaf(scp[q * 64 + k], Vs[k * 64 + half * 32 + d2], o);
        orow[d2] = f2tf32f(o);
    }
}

// ---------------- streams / events ----------------
#define DSM8 (3 * (ASZ + 32 * 136) * 4)
#define DSM4 (3 * (ASZ + 32 * 72) * 4)
#define DSMA ((4096 + 4096 + 8192) * 4)
struct SfStreams {
    cudaStream_t s1, s2;
    cudaEvent_t e_root, e_pre, e_inits, e_sample, e_wout, e_t2, e_proj, e_outi;
    SfStreams() {
        cudaStreamCreateWithFlags(&s1, cudaStreamNonBlocking);
        cudaStreamCreateWithFlags(&s2, cudaStreamNonBlocking);
        cudaEventCreateWithFlags(&e_root,   cudaEventDisableTiming);
        cudaEventCreateWithFlags(&e_pre,    cudaEventDisableTiming);
        cudaEventCreateWithFlags(&e_inits,  cudaEventDisableTiming);
        cudaEventCreateWithFlags(&e_sample, cudaEventDisableTiming);
        cudaEventCreateWithFlags(&e_wout,   cudaEventDisableTiming);
        cudaEventCreateWithFlags(&e_t2,     cudaEventDisableTiming);
        cudaEventCreateWithFlags(&e_proj,   cudaEventDisableTiming);
        cudaEventCreateWithFlags(&e_outi,   cudaEventDisableTiming);
        cudaFuncSetAttribute(mma_gemm_t<8>, cudaFuncAttributeMaxDynamicSharedMemorySize, DSM8);
        cudaFuncSetAttribute(mma_gemm_t<4>, cudaFuncAttributeMaxDynamicSharedMemorySize, DSM4);
        cudaFuncSetAttribute(mixmma_k, cudaFuncAttributeMaxDynamicSharedMemorySize, MXH_TOTAL);
        cudaFuncSetAttribute(attn_k, cudaFuncAttributeMaxDynamicSharedMemorySize, DSMA);
    }
};
static SfStreams g_sf;

// ---------------- launch ----------------
extern "C" void kernel_launch(void* const* d_in, const int* in_sizes, int n_in,
                              void* d_out, int out_size) {
    const float* token_embed = (const float*)d_in[0];
    const float* token_roi   = (const float*)d_in[1];
    const float* img_feat    = (const float*)d_in[2];
    const float* ln_off_g    = (const float*)d_in[3];
    const float* ln_off_b    = (const float*)d_in[4];
    const float* w_off       = (const float*)d_in[5];
    const float* off_bias    = (const float*)d_in[6];
    const float* ln_pg_g     = (const float*)d_in[7];
    const float* ln_pg_b     = (const float*)d_in[8];
    const float* w_pg1       = (const float*)d_in[9];
    const float* b_pg1       = (const float*)d_in[10];
    const float* w_pg2       = (const float*)d_in[11];
    const float* b_pg2       = (const float*)d_in[12];
    const float* m_beta      = (const float*)d_in[13];
    const float* s_beta      = (const float*)d_in[14];
    const float* w_out       = (const float*)d_in[15];
    const float* b_out       = (const float*)d_in[16];
    const float* ln1_g       = (const float*)d_in[17];
    const float* ln1_b       = (const float*)d_in[18];
    const float* w_qkv       = (const float*)d_in[19];
    const float* b_qkv       = (const float*)d_in[20];
    const float* w_proj      = (const float*)d_in[21];
    const float* b_proj      = (const float*)d_in[22];
    const float* ln2_g       = (const float*)d_in[23];
    const float* ln2_b       = (const float*)d_in[24];
    const float* w_fc1       = (const float*)d_in[25];
    const float* b_fc1       = (const float*)d_in[26];
    const float* w_fc2       = (const float*)d_in[27];
    const float* b_fc2       = (const float*)d_in[28];
    float* out = (float*)d_out;

    void* p;
    cudaGetSymbolAddress(&p, g_hidden);    float* hidden  = (float*)p;
    cudaGetSymbolAddress(&p, g_params_h);  __half* ph     = (__half*)p;
    cudaGetSymbolAddress(&p, g_h);         float* hbuf    = (float*)p;
    cudaGetSymbolAddress(&p, g_tok);       float* tok     = (float*)p;
    cudaGetSymbolAddress(&p, g_tok2);      float* tok2    = (float*)p;
    cudaGetSymbolAddress(&p, g_x);         float* xbuf    = (float*)p;
    cudaGetSymbolAddress(&p, g_qkv);       float* qkv     = (float*)p;
    cudaGetSymbolAddress(&p, g_attout);    float* attout  = (float*)p;
    cudaGetSymbolAddress(&p, g_ff);        float* ff      = (float*)p;

    cudaStream_t s0 = 0, s1 = g_sf.s1, s2 = g_sf.s2;

    // ---- fork ----
    cudaEventRecord(g_sf.e_root, s0);
    cudaStreamWaitEvent(s1, g_sf.e_root, 0);
    cudaStreamWaitEvent(s2, g_sf.e_root, 0);

    // s0: pre_k -> params GEMM (fp16 output)
    pre_k<<<TKN, 128, 0, s0>>>(token_embed, token_roi, ln_off_g, ln_off_b, w_off, off_bias,
                               ln_pg_g, ln_pg_b, w_pg1, b_pg1);
    cudaEventRecord(g_sf.e_pre, s0);
    mma_gemm_t<8><<<dim3((TOTN + 127) / 128, TKN / 128, 1), 256, DSM8, s0>>>(
        hidden, w_pg2, b_pg2, nullptr, ph, TKN, TOTN, PGN, 0, 0);

    // s1: fused init
    init2_k<<<(TKN * DIM + TKN * 3 * DIM + 255) / 256, 256, 0, s1>>>(
        token_embed, b_out, b_qkv, tok, qkv);
    cudaEventRecord(g_sf.e_inits, s1);

    // s2: transpose, then sampling
    transpose_k<<<dim3((HGT * WID) / 32, CCH / 32, 8), 256, 0, s2>>>(img_feat);
    cudaStreamWaitEvent(s2, g_sf.e_pre, 0);
    sample_k<<<dim3(PPT, TKN), 64, 0, s2>>>();
    cudaEventRecord(g_sf.e_sample, s2);

    // s0: mixing (fp16 HMMA)
    cudaStreamWaitEvent(s0, g_sf.e_sample, 0);
    mixmma_k<<<TKN, 256, MXH_TOTAL, s0>>>(m_beta, s_beta);

    // s0: w_out GEMM (TN=4, splitK16)
    cudaStreamWaitEvent(s0, g_sf.e_inits, 0);
    mma_gemm_t<4><<<dim3(DIM / 64, TKN / 128, 16), 256, DSM4, s0>>>(
        hbuf, w_out, nullptr, tok, nullptr, TKN, DIM, PPT * CCH, 0, 0);
    cudaEventRecord(g_sf.e_wout, s0);

    // s1: init_tok2
    cudaStreamWaitEvent(s1, g_sf.e_wout, 0);
    init_k<<<(TKN * DIM + 255) / 256, 256, 0, s1>>>(tok, b_proj, tok2, TKN * DIM, DIM);
    cudaEventRecord(g_sf.e_t2, s1);

    // s0: LN1 -> qkv -> attention
    ln_k<<<TKN, 128, 0, s0>>>(tok, ln1_g, ln1_b, xbuf);
    mma_gemm_t<4><<<dim3((3 * DIM) / 64, TKN / 128, 4), 256, DSM4, s0>>>(
        xbuf, w_qkv, nullptr, qkv, nullptr, TKN, 3 * DIM, DIM, 0, 0);
    attn_k<<<dim3(8, 8), 128, DSMA, s0>>>();
    // s0: proj
    cudaStreamWaitEvent(s0, g_sf.e_t2, 0);
    mma_gemm_t<4><<<dim3(DIM / 64, TKN / 128, 8), 256, DSM4, s0>>>(
        attout, w_proj, nullptr, tok2, nullptr, TKN, DIM, DIM, 0, 0);
    cudaEventRecord(g_sf.e_proj, s0);

    // s2: init_out
    cudaStreamWaitEvent(s2, g_sf.e_proj, 0);
    init_k<<<(TKN * DIM + 255) / 256, 256, 0, s2>>>(tok2, b_fc2, out, TKN * DIM, DIM);
    cudaEventRecord(g_sf.e_outi, s2);

    // s0: LN2 -> fc1 (fused bias+gelu) -> fc2
    ln_k<<<TKN, 128, 0, s0>>>(tok2, ln2_g, ln2_b, xbuf);
    mma_gemm_t<4><<<dim3((4 * DIM) / 64, TKN / 128, 1), 256, DSM4, s0>>>(
        xbuf, w_fc1, b_fc1, ff, nullptr, TKN, 4 * DIM, DIM, 0, 1);
    cudaStreamWaitEvent(s0, g_sf.e_outi, 0);
    mma_gemm_t<4><<<dim3(DIM / 64, TKN / 128, 16), 256, DSM4, s0>>>(
        ff, w_fc2, nullptr, out, nullptr, TKN, DIM, 4 * DIM, 0, 0);
}

// round 17
// speedup vs baseline: 1.2776x; 1.0830x over previous
#include <cuda_runtime.h>
#include <cuda_fp16.h>
#include <math.h>
#include <stdint.h>

// ---------------- constants ----------------
#define TKN 512
#define DIM 512
#define CCH 256
#define HGT 128
#define WID 128
#define PPT 36
#define PGN 128
#define TOTN 66832
#define CC2 65536

// ---------------- scratch ----------------
__device__ float g_imgT[8 * HGT * WID * CCH];
__device__ float g_hidden[TKN * PGN];
__device__ float g_grid[TKN * PPT * 2];
__device__ __half g_params_h[(size_t)TKN * TOTN];
__device__ float g_sampled[TKN * PPT * CCH];
__device__ __half g_h_h[TKN * PPT * CCH];
__device__ float g_tok[TKN * DIM];
__device__ float g_tok2[TKN * DIM];
__device__ __half g_x_h[TKN * DIM];
__device__ float g_qkv[TKN * 3 * DIM];
__device__ __half g_att_h[TKN * DIM];
__device__ __half g_ff_h[TKN * 4 * DIM];
// fp16 weight copies
__device__ __half h_wout[PPT * CCH * DIM];
__device__ __half h_wqkv[DIM * 3 * DIM];
__device__ __half h_wproj[DIM * DIM];
__device__ __half h_wfc1[DIM * 4 * DIM];
__device__ __half h_wfc2[4 * DIM * DIM];

__device__ __forceinline__ float gelu_f(float x) {
    return 0.5f * x * (1.0f + erff(x * 0.70710678118654752440f));
}
__device__ __forceinline__ float f2tf32f(float x) {
    uint32_t r;
    asm("cvt.rna.tf32.f32 %0, %1;" : "=r"(r) : "f"(x));
    return __uint_as_float(r);
}
__device__ __forceinline__ void red2f(float* p, float a, float b) {
    asm volatile("red.global.add.v2.f32 [%0], {%1, %2};"
                 :: "l"(p), "f"(a), "f"(b) : "memory");
}

// ---------------- weight fp32 -> fp16 (one launch, s1) ----------------
#define W1 (PPT * CCH * DIM / 4)
#define W2 (DIM * 3 * DIM / 4)
#define W3 (DIM * DIM / 4)
#define W4 (DIM * 4 * DIM / 4)
#define W5 (4 * DIM * DIM / 4)
#define WC2 (W1)
#define WC3 (WC2 + W2)
#define WC4 (WC3 + W3)
#define WC5 (WC4 + W4)
#define WCT (WC5 + W5)
__global__ void w2h_k(const float* __restrict__ w1, const float* __restrict__ w2,
                      const float* __restrict__ w3, const float* __restrict__ w4,
                      const float* __restrict__ w5) {
    int i = blockIdx.x * 256 + threadIdx.x;
    if (i >= WCT) return;
    const float* src; __half* dst; int off;
    if      (i < WC2) { src = w1; dst = h_wout;  off = i; }
    else if (i < WC3) { src = w2; dst = h_wqkv;  off = i - WC2; }
    else if (i < WC4) { src = w3; dst = h_wproj; off = i - WC3; }
    else if (i < WC5) { src = w4; dst = h_wfc1;  off = i - WC4; }
    else              { src = w5; dst = h_wfc2;  off = i - WC5; }
    float4 v = ((const float4*)src)[off];
    ((__half2*)dst)[2 * off]     = __floats2half2_rn(v.x, v.y);
    ((__half2*)dst)[2 * off + 1] = __floats2half2_rn(v.z, v.w);
}

// ---------------- img transpose ----------------
__global__ void transpose_k(const float* __restrict__ in) {
    __shared__ float tile[32][33];
    int b = blockIdx.z;
    int s0 = blockIdx.x * 32;
    int c0 = blockIdx.y * 32;
    const float* ib = in + (size_t)b * CCH * HGT * WID;
    float* ob = g_imgT + (size_t)b * HGT * WID * CCH;
    int tid = threadIdx.x;
    {
        int c = tid >> 3, s4 = tid & 7;
        float4 v = *(const float4*)(ib + (size_t)(c0 + c) * (HGT * WID) + s0 + 4 * s4);
        tile[4 * s4 + 0][c] = v.x;
        tile[4 * s4 + 1][c] = v.y;
        tile[4 * s4 + 2][c] = v.z;
        tile[4 * s4 + 3][c] = v.w;
    }
    __syncthreads();
    {
        int g = tid & 7, s = tid >> 3;
        float4 v;
        v.x = tile[s][4 * g + 0];
        v.y = tile[s][4 * g + 1];
        v.z = tile[s][4 * g + 2];
        v.w = tile[s][4 * g + 3];
        *(float4*)(ob + (size_t)(s0 + s) * CCH + c0 + 4 * g) = v;
    }
}

// ---------------- per-token pre ----------------
__global__ void pre_k(const float* __restrict__ x, const float* __restrict__ roi,
                      const float* __restrict__ g_off, const float* __restrict__ b_off,
                      const float* __restrict__ w_off, const float* __restrict__ off_bias,
                      const float* __restrict__ g_pg, const float* __restrict__ b_pg,
                      const float* __restrict__ w_pg1, const float* __restrict__ b_pg1) {
    int t = blockIdx.x;
    int tid = threadIdx.x;
    __shared__ float xoff[DIM], xpg[DIM], offs[72];
    __shared__ float rs[4], rs2[4], stats[4];

    const float* xr = x + (size_t)t * DIM;
    float v[4], s = 0.f, s2 = 0.f;
#pragma unroll
    for (int i = 0; i < 4; i++) { v[i] = xr[tid + 128 * i]; s += v[i]; s2 += v[i] * v[i]; }
#pragma unroll
    for (int o = 16; o; o >>= 1) {
        s  += __shfl_down_sync(0xffffffffu, s,  o);
        s2 += __shfl_down_sync(0xffffffffu, s2, o);
    }
    if ((tid & 31) == 0) { rs[tid >> 5] = s; rs2[tid >> 5] = s2; }
    __syncthreads();
    float ts = rs[0] + rs[1] + rs[2] + rs[3];
    float ts2 = rs2[0] + rs2[1] + rs2[2] + rs2[3];
    float mean = ts * (1.f / DIM);
    float var = ts2 * (1.f / DIM) - mean * mean;
    float rstd = rsqrtf(var + 1e-5f);
#pragma unroll
    for (int i = 0; i < 4; i++) {
        int k = tid + 128 * i;
        float xn = (v[i] - mean) * rstd;
        xoff[k] = xn * g_off[k] + b_off[k];
        xpg[k]  = xn * g_pg[k]  + b_pg[k];
    }
    __syncthreads();

    {
        float h = b_pg1[tid];
        for (int k = 0; k < DIM; k++) h = fmaf(xpg[k], w_pg1[k * PGN + tid], h);
        g_hidden[t * PGN + tid] = f2tf32f(h);
    }
    if (tid < 72) {
        float o = off_bias[tid];
        for (int k = 0; k < DIM; k++) o = fmaf(xoff[k], w_off[k * 72 + tid], o);
        offs[tid] = o;
    }
    __syncthreads();
    if (tid < 2) {
        float mu = 0.f;
        for (int p = 0; p < PPT; p++) mu += offs[p * 2 + tid];
        mu *= (1.f / PPT);
        float vv = 0.f;
        for (int p = 0; p < PPT; p++) { float d = offs[p * 2 + tid] - mu; vv += d * d; }
        vv *= (1.f / (PPT - 1));
        stats[tid * 2] = mu;
        stats[tid * 2 + 1] = sqrtf(vv) + 1e-5f;
    }
    __syncthreads();
    if (tid < 72) {
        int coord = tid & 1, p = tid >> 1;
        float mu = stats[coord * 2], sd = stats[coord * 2 + 1];
        float on = (offs[tid] - mu) / (3.f * sd);
        float tl = roi[t * 4 + coord], br = roi[t * 4 + 2 + coord];
        float xy = 0.5f * (tl + br), wh = br - tl;
        float pt = xy + on * wh;
        g_grid[(t * PPT + p) * 2 + coord] = pt * 2.f - 1.f;
    }
}

// ---------------- bilinear grid sample ----------------
__global__ void sample_k() {
    int p = blockIdx.x, t = blockIdx.y;
    int c4 = threadIdx.x << 2;
    int b = t >> 6;
    float gx = g_grid[(t * PPT + p) * 2 + 0];
    float gy = g_grid[(t * PPT + p) * 2 + 1];
    float x = ((gx + 1.f) * WID - 1.f) * 0.5f;
    float y = ((gy + 1.f) * HGT - 1.f) * 0.5f;
    float x0f = floorf(x), y0f = floorf(y);
    float wx = x - x0f, wy = y - y0f;
    int x0 = min(max((int)x0f, 0), WID - 1);
    int x1 = min(max((int)x0f + 1, 0), WID - 1);
    int y0 = min(max((int)y0f, 0), HGT - 1);
    int y1 = min(max((int)y0f + 1, 0), HGT - 1);
    const float* ib = g_imgT + (size_t)b * HGT * WID * CCH;
    float4 v00 = *(const float4*)(ib + (size_t)(y0 * WID + x0) * CCH + c4);
    float4 v01 = *(const float4*)(ib + (size_t)(y0 * WID + x1) * CCH + c4);
    float4 v10 = *(const float4*)(ib + (size_t)(y1 * WID + x0) * CCH + c4);
    float4 v11 = *(const float4*)(ib + (size_t)(y1 * WID + x1) * CCH + c4);
    float w00 = (1.f - wx) * (1.f - wy), w01 = wx * (1.f - wy);
    float w10 = (1.f - wx) * wy,         w11 = wx * wy;
    float4 o;
    o.x = v00.x * w00 + v01.x * w01 + v10.x * w10 + v11.x * w11;
    o.y = v00.y * w00 + v01.y * w01 + v10.y * w10 + v11.y * w11;
    o.z = v00.z * w00 + v01.z * w01 + v10.z * w10 + v11.z * w11;
    o.w = v00.w * w00 + v01.w * w01 + v10.w * w10 + v11.w * w11;
    *(float4*)(g_sampled + ((size_t)t * PPT + p) * CCH + c4) = o;
}

// ---------------- cp.async helpers ----------------
__device__ __forceinline__ void cpa16(uint32_t dst, const void* src, bool pred) {
    int sz = pred ? 16 : 0;
    asm volatile("cp.async.cg.shared.global [%0], [%1], 16, %2;"
                 :: "r"(dst), "l"(src), "r"(sz));
}
__device__ __forceinline__ void cpa_commit() {
    asm volatile("cp.async.commit_group;");
}
__device__ __forceinline__ uint32_t smem_u32(const void* p) {
    uint32_t a;
    asm("{ .reg .u64 t; cvta.to.shared.u64 t, %1; cvt.u32.u64 %0, t; }" : "=r"(a) : "l"(p));
    return a;
}

// ---------------- tf32 GEMM (params only): fp32 A/B, fp16 C out ----------------
#define ASZ 4608
template <int TN>
__global__ void __launch_bounds__(256)
mma_gemm_t(const float* __restrict__ A, const float* __restrict__ Bm,
           const float* __restrict__ bias, __half* __restrict__ C16,
           int M, int N, int K) {
    constexpr int BN   = TN * 16;
    constexpr int BSTR = BN + 8;
    constexpr int BSZf = 32 * BSTR;
    constexpr int STGf = ASZ + BSZf;
    constexpr int BIT  = BN / 32;
    constexpr int BQ   = BN / 4;

    extern __shared__ float smf[];
    uint32_t sbase = smem_u32(smf);

    int tid = threadIdx.x;
    int warp = tid >> 5, lane = tid & 31;
    int wr = (warp >> 1) * 32;
    int wc = (warp & 1) * (TN * 8);
    int bR = blockIdx.y * 128, bC = blockIdx.x * BN;
    int ntiles = K >> 5;

    float acc[2][TN][4];
#pragma unroll
    for (int a = 0; a < 2; a++)
#pragma unroll
        for (int b = 0; b < TN; b++)
#pragma unroll
            for (int c = 0; c < 4; c++) acc[a][b][c] = 0.f;

    int ar[4], ac[4];
#pragma unroll
    for (int i = 0; i < 4; i++) {
        int f = tid + (i << 8);
        ar[i] = f >> 3;  ac[i] = (f & 7) << 2;
    }
    int br_[BIT], bc_[BIT];
#pragma unroll
    for (int i = 0; i < BIT; i++) {
        int f = tid + (i << 8);
        br_[i] = f / BQ; bc_[i] = (f % BQ) << 2;
    }

    auto issue = [&](int t, int stage) {
        int k0 = t << 5;
        uint32_t sa = sbase + stage * (STGf * 4);
#pragma unroll
        for (int i = 0; i < 4; i++) {
            cpa16(sa + (ar[i] * 36 + ac[i]) * 4,
                  A + (size_t)(bR + ar[i]) * K + k0 + ac[i], true);
        }
        uint32_t sb = sa + ASZ * 4;
#pragma unroll
        for (int i = 0; i < BIT; i++) {
            int gc = bC + bc_[i];
            cpa16(sb + (br_[i] * BSTR + bc_[i]) * 4,
                  Bm + (size_t)(k0 + br_[i]) * N + gc, gc < N);
        }
        cpa_commit();
    };

    issue(0, 0);
    if (ntiles > 1) issue(1, 1);
    int rd = 0, wrb = 2;
    for (int t = 0; t < ntiles; t++) {
        if (t + 1 < ntiles) {
            asm volatile("cp.async.wait_group 1;");
        } else {
            asm volatile("cp.async.wait_group 0;");
        }
        __syncthreads();
        if (t + 2 < ntiles) {
            issue(t + 2, wrb);
            wrb = (wrb == 2) ? 0 : wrb + 1;
        }
        const uint32_t* As = (const uint32_t*)(smf + rd * STGf);
        const uint32_t* Bs = As + ASZ;
        rd = (rd == 2) ? 0 : rd + 1;
#pragma unroll
        for (int k8 = 0; k8 < 4; k8++) {
            int kk = k8 << 3;
            uint32_t afr[2][4];
#pragma unroll
            for (int tm = 0; tm < 2; tm++) {
                int r = wr + tm * 16 + (lane >> 2);
                int c = kk + (lane & 3);
                afr[tm][0] = As[r * 36 + c];
                afr[tm][1] = As[(r + 8) * 36 + c];
                afr[tm][2] = As[r * 36 + c + 4];
                afr[tm][3] = As[(r + 8) * 36 + c + 4];
            }
#pragma unroll
            for (int tn = 0; tn < TN; tn++) {
                int col = wc + tn * 8 + (lane >> 2);
                uint32_t b0 = Bs[(kk + (lane & 3)) * BSTR + col];
                uint32_t b1 = Bs[(kk + (lane & 3) + 4) * BSTR + col];
#pragma unroll
                for (int tm = 0; tm < 2; tm++) {
                    asm volatile(
                        "mma.sync.aligned.m16n8k8.row.col.f32.tf32.tf32.f32 "
                        "{%0,%1,%2,%3}, {%4,%5,%6,%7}, {%8,%9}, {%0,%1,%2,%3};"
                        : "+f"(acc[tm][tn][0]), "+f"(acc[tm][tn][1]),
                          "+f"(acc[tm][tn][2]), "+f"(acc[tm][tn][3])
                        : "r"(afr[tm][0]), "r"(afr[tm][1]),
                          "r"(afr[tm][2]), "r"(afr[tm][3]),
                          "r"(b0), "r"(b1));
                }
            }
        }
    }

#pragma unroll
    for (int tm = 0; tm < 2; tm++) {
        int row = bR + wr + tm * 16 + (lane >> 2);
#pragma unroll
        for (int tn = 0; tn < TN; tn++) {
            int col = bC + wc + tn * 8 + ((lane & 3) << 1);
            if (col >= N) continue;
            float bv0 = bias[col], bv1 = bias[col + 1];
            *(__half2*)(C16 + (size_t)row * N + col) =
                __floats2half2_rn(acc[tm][tn][0] + bv0, acc[tm][tn][1] + bv1);
            *(__half2*)(C16 + (size_t)(row + 8) * N + col) =
                __floats2half2_rn(acc[tm][tn][2] + bv0, acc[tm][tn][3] + bv1);
        }
    }
}

// ---------------- fp16 GEMM: A fp16 k-major, B fp16, m16n8k16 ----------------
// 128 x (TN*16) tile; 3-buffer cp.async; 1 barrier/ktile(32).
// nz>1: red2f into pre-initialized fp32 C. nz==1 + act: gelu -> fp16 C16.
#define HASZ (128 * 40)   // halves per A stage
template <int TN>
__global__ void __launch_bounds__(256)
mma_gemm_h(const __half* __restrict__ A, const __half* __restrict__ Bm,
           const float* __restrict__ bias, float* __restrict__ C,
           __half* __restrict__ C16, int M, int N, int K, int act) {
    constexpr int BN   = TN * 16;
    constexpr int BSTR = BN + 8;           // halves
    constexpr int BSZh = 32 * BSTR;
    constexpr int STGh = HASZ + BSZh;      // halves per stage
    constexpr int BCH  = BN / 8;           // 16B chunks per B row
    constexpr int BITh = (32 * BCH) / 256; // B-load iters per thread

    extern __shared__ __align__(16) __half smh[];
    uint32_t sbase = smem_u32(smh);

    int tid = threadIdx.x;
    int warp = tid >> 5, lane = tid & 31;
    int g = lane >> 2, tt = lane & 3;
    int wr = (warp >> 1) * 32;
    int wc = (warp & 1) * (TN * 8);
    int bR = blockIdx.y * 128, bC = blockIdx.x * BN;
    int nz = gridDim.z;
    int Kc = K / nz;
    int kbeg = blockIdx.z * Kc;
    int ntiles = Kc >> 5;

    float acc[2][TN][4];
#pragma unroll
    for (int a = 0; a < 2; a++)
#pragma unroll
        for (int b = 0; b < TN; b++)
#pragma unroll
            for (int c = 0; c < 4; c++) acc[a][b][c] = 0.f;

    auto issue = [&](int t, int stage) {
        int k0 = kbeg + (t << 5);
        uint32_t sa = sbase + stage * (STGh * 2);
#pragma unroll
        for (int i = 0; i < 2; i++) {
            int f = tid + (i << 8);
            int r = f >> 2, c8 = (f & 3) << 3;
            cpa16(sa + (r * 40 + c8) * 2,
                  A + (size_t)(bR + r) * K + k0 + c8, true);
        }
        uint32_t sb = sa + HASZ * 2;
#pragma unroll
        for (int i = 0; i < BITh; i++) {
            int f = tid + (i << 8);
            int r = f / BCH, c8 = (f % BCH) * 8;
            int gc = bC + c8;
            cpa16(sb + (r * BSTR + c8) * 2,
                  Bm + (size_t)(k0 + r) * N + gc, gc < N);
        }
        cpa_commit();
    };

    issue(0, 0);
    if (ntiles > 1) issue(1, 1);
    int rd = 0, wrb = 2;
    for (int t = 0; t < ntiles; t++) {
        if (t + 1 < ntiles) {
            asm volatile("cp.async.wait_group 1;");
        } else {
            asm volatile("cp.async.wait_group 0;");
        }
        __syncthreads();
        if (t + 2 < ntiles) {
            issue(t + 2, wrb);
            wrb = (wrb == 2) ? 0 : wrb + 1;
        }
        const __half* Ah = smh + rd * STGh;
        uint32_t bb = sbase + (rd * STGh + HASZ) * 2;
        rd = (rd == 2) ? 0 : rd + 1;
#pragma unroll
        for (int ks = 0; ks < 2; ks++) {
            int c0 = (ks << 4) + (tt << 1);
            uint32_t afr[2][4];
#pragma unroll
            for (int tm = 0; tm < 2; tm++) {
                const __half* ap = Ah + (wr + tm * 16 + g) * 40 + c0;
                afr[tm][0] = *(const uint32_t*)ap;
                afr[tm][1] = *(const uint32_t*)(ap + 8 * 40);
                afr[tm][2] = *(const uint32_t*)(ap + 8);
                afr[tm][3] = *(const uint32_t*)(ap + 8 * 40 + 8);
            }
#pragma unroll
            for (int tn = 0; tn < TN; tn++) {
                int n0 = wc + tn * 8;
                uint32_t baddr = bb + (((ks << 4) + (lane & 15)) * BSTR + n0) * 2;
                uint32_t b0, b1;
                asm volatile(
                    "ldmatrix.sync.aligned.m8n8.x2.trans.shared.b16 {%0,%1}, [%2];"
                    : "=r"(b0), "=r"(b1) : "r"(baddr));
#pragma unroll
                for (int tm = 0; tm < 2; tm++) {
                    asm volatile(
                        "mma.sync.aligned.m16n8k16.row.col.f32.f16.f16.f32 "
                        "{%0,%1,%2,%3}, {%4,%5,%6,%7}, {%8,%9}, {%0,%1,%2,%3};"
                        : "+f"(acc[tm][tn][0]), "+f"(acc[tm][tn][1]),
                          "+f"(acc[tm][tn][2]), "+f"(acc[tm][tn][3])
                        : "r"(afr[tm][0]), "r"(afr[tm][1]),
                          "r"(afr[tm][2]), "r"(afr[tm][3]),
                          "r"(b0), "r"(b1));
                }
            }
        }
    }

    if (nz == 1) {
#pragma unroll
        for (int tm = 0; tm < 2; tm++) {
            int row = bR + wr + tm * 16 + g;
#pragma unroll
            for (int tn = 0; tn < TN; tn++) {
                int col = bC + wc + tn * 8 + (tt << 1);
                if (col >= N) continue;
                float bv0 = bias ? bias[col] : 0.f;
                float bv1 = bias ? bias[col + 1] : 0.f;
                float o0 = acc[tm][tn][0] + bv0, o1 = acc[tm][tn][1] + bv1;
                float o2 = acc[tm][tn][2] + bv0, o3 = acc[tm][tn][3] + bv1;
                if (act) {
                    o0 = gelu_f(o0); o1 = gelu_f(o1);
                    o2 = gelu_f(o2); o3 = gelu_f(o3);
                }
                if (C16) {
                    *(__half2*)(C16 + (size_t)row * N + col) = __floats2half2_rn(o0, o1);
                    *(__half2*)(C16 + (size_t)(row + 8) * N + col) = __floats2half2_rn(o2, o3);
                } else {
                    *(float2*)(&C[(size_t)row * N + col])       = make_float2(o0, o1);
                    *(float2*)(&C[(size_t)(row + 8) * N + col]) = make_float2(o2, o3);
                }
            }
        }
    } else {
#pragma unroll
        for (int tm = 0; tm < 2; tm++) {
            int row = bR + wr + tm * 16 + g;
#pragma unroll
            for (int tn = 0; tn < TN; tn++) {
                int col = bC + wc + tn * 8 + (tt << 1);
                red2f(&C[(size_t)row * N + col], acc[tm][tn][0], acc[tm][tn][1]);
                red2f(&C[(size_t)(row + 8) * N + col], acc[tm][tn][2], acc[tm][tn][3]);
            }
        }
    }
}

// ---------------- fused early init ----------------
__global__ void init2_k(const float* __restrict__ resid, const float* __restrict__ b_out,
                        const float* __restrict__ b_qkv,
                        float* __restrict__ tok, float* __restrict__ qkv) {
    int i = blockIdx.x * 256 + threadIdx.x;
    if (i < TKN * DIM) {
        tok[i] = resid[i] + b_out[i & (DIM - 1)];
    }
    int j = i - TKN * DIM;
    if (j >= 0 && j < TKN * 3 * DIM) {
        qkv[j] = b_qkv[j % (3 * DIM)];
    }
}

__global__ void init_k(const float* __restrict__ resid, const float* __restrict__ bias,
                       float* __restrict__ C, int n, int N) {
    int i = blockIdx.x * 256 + threadIdx.x;
    if (i < n) {
        int col = i % N;
        C[i] = (resid ? resid[i] : 0.f) + bias[col];
    }
}

// ---------------- fp16 tensor-core per-token mixing (fp16 h output) ----------------
#define MXH_ABYTES (48 * 264 * 2)
#define MXH_BSTAGE (32 * 264 * 2)
#define MXH_SMSOFF (MXH_ABYTES + 2 * MXH_BSTAGE)
#define MXH_TOTAL  (MXH_SMSOFF + 1296 * 4)
__global__ void __launch_bounds__(256)
mixmma_k(const float* __restrict__ mb, const float* __restrict__ sb) {
    extern __shared__ __align__(16) char smx[];
    __half* Ah  = (__half*)smx;
    float*  sms = (float*)(smx + MXH_SMSOFF);
    float*  hsh = (float*)smx;
    uint32_t sbase = smem_u32(smx);

    int t = blockIdx.x, tid = threadIdx.x;
    int warp = tid >> 5, lane = tid & 31;
    const __half* ph = g_params_h + (size_t)t * TOTN;

    const float* sp = g_sampled + (size_t)t * (PPT * CCH);
    for (int i = tid; i < PPT * CCH / 2; i += 256) {
        int r = i >> 7, c2 = (i & 127) << 1;
        float2 v = *(const float2*)(sp + r * 256 + c2);
        *(__half2*)(Ah + r * 264 + c2) = __floats2half2_rn(v.x, v.y);
    }
    for (int i = tid; i < 12 * 264 / 2; i += 256)
        ((uint32_t*)(Ah + 36 * 264))[i] = 0u;
    for (int i = tid; i < PPT * PPT; i += 256)
        sms[i] = __half2float(ph[CC2 + i]);

    auto issue = [&](int ch, int stg) {
        const __half* src = ph + ch * 8192;
        uint32_t dst = sbase + MXH_ABYTES + stg * MXH_BSTAGE;
#pragma unroll
        for (int i = 0; i < 4; i++) {
            int e = tid + (i << 8);
            int r = e >> 5, c8 = (e & 31) << 3;
            cpa16(dst + (r * 264 + c8) * 2, src + r * 256 + c8, true);
        }
        cpa_commit();
    };

    float acc[3][4][4];
#pragma unroll
    for (int a = 0; a < 3; a++)
#pragma unroll
        for (int b = 0; b < 4; b++)
#pragma unroll
            for (int c = 0; c < 4; c++) acc[a][b][c] = 0.f;

    int g = lane >> 2, tt = lane & 3;
    issue(0, 0);
    for (int ch = 0; ch < 8; ch++) {
        if (ch + 1 < 8) {
            issue(ch + 1, (ch + 1) & 1);
            asm volatile("cp.async.wait_group 1;");
        } else {
            asm volatile("cp.async.wait_group 0;");
        }
        __syncthreads();
        uint32_t bbase = sbase + MXH_ABYTES + (ch & 1) * MXH_BSTAGE;
#pragma unroll
        for (int ks = 0; ks < 2; ks++) {
            int c0 = (ch << 5) + (ks << 4) + (tt << 1);
            uint32_t afr[3][4];
#pragma unroll
            for (int mt = 0; mt < 3; mt++) {
                const __half* ap = Ah + (mt * 16 + g) * 264 + c0;
                afr[mt][0] = *(const uint32_t*)ap;
                afr[mt][1] = *(const uint32_t*)(ap + 8 * 264);
                afr[mt][2] = *(const uint32_t*)(ap + 8);
                afr[mt][3] = *(const uint32_t*)(ap + 8 * 264 + 8);
            }
#pragma unroll
            for (int tn = 0; tn < 4; tn++) {
                int n0 = warp * 32 + tn * 8;
                uint32_t baddr = bbase + (((ks << 4) + (lane & 15)) * 264 + n0) * 2;
                uint32_t b0, b1;
                asm volatile(
                    "ldmatrix.sync.aligned.m8n8.x2.trans.shared.b16 {%0,%1}, [%2];"
                    : "=r"(b0), "=r"(b1) : "r"(baddr));
#pragma unroll
                for (int mt = 0; mt < 3; mt++) {
                    asm volatile(
                        "mma.sync.aligned.m16n8k16.row.col.f32.f16.f16.f32 "
                        "{%0,%1,%2,%3}, {%4,%5,%6,%7}, {%8,%9}, {%0,%1,%2,%3};"
                        : "+f"(acc[mt][tn][0]), "+f"(acc[mt][tn][1]),
                          "+f"(acc[mt][tn][2]), "+f"(acc[mt][tn][3])
                        : "r"(afr[mt][0]), "r"(afr[mt][1]),
                          "r"(afr[mt][2]), "r"(afr[mt][3]),
                          "r"(b0), "r"(b1));
                }
            }
        }
        __syncthreads();
    }

#pragma unroll
    for (int mt = 0; mt < 3; mt++) {
#pragma unroll
        for (int half = 0; half < 2; half++) {
            int row = mt * 16 + g + half * 8;
            if (row >= PPT) continue;
#pragma unroll
            for (int tn = 0; tn < 4; tn++) {
                int col = warp * 32 + tn * 8 + (tt << 1);
                hsh[row * 260 + col]     = gelu_f(acc[mt][tn][half * 2 + 0] + mb[col]);
                hsh[row * 260 + col + 1] = gelu_f(acc[mt][tn][half * 2 + 1] + mb[col + 1]);
            }
        }
    }
    __syncthreads();

    int d4 = tid & 63;
    int q0 = (tid >> 6) * 9;
    float4 accq[9];
#pragma unroll
    for (int q = 0; q < 9; q++) {
        float s = sb[q0 + q];
        accq[q] = make_float4(s, s, s, s);
    }
    for (int p = 0; p < PPT; p++) {
        float4 hv = *(const float4*)(hsh + p * 260 + 4 * d4);
#pragma unroll
        for (int q = 0; q < 9; q++) {
            float smv = sms[(q0 + q) * PPT + p];
            accq[q].x = fmaf(smv, hv.x, accq[q].x);
            accq[q].y = fmaf(smv, hv.y, accq[q].y);
            accq[q].z = fmaf(smv, hv.z, accq[q].z);
            accq[q].w = fmaf(smv, hv.w, accq[q].w);
        }
    }
    __half* ho = g_h_h + (size_t)t * (PPT * CCH);
#pragma unroll
    for (int q = 0; q < 9; q++) {
        __half2 p0 = __floats2half2_rn(gelu_f(accq[q].x), gelu_f(accq[q].y));
        __half2 p1 = __floats2half2_rn(gelu_f(accq[q].z), gelu_f(accq[q].w));
        *(__half2*)(ho + (q0 + q) * CCH + 4 * d4)     = p0;
        *(__half2*)(ho + (q0 + q) * CCH + 4 * d4 + 2) = p1;
    }
}

// ---------------- layernorm (fp16 output) ----------------
__global__ void ln_k(const float* __restrict__ x, const float* __restrict__ g,
                     const float* __restrict__ bb, __half* __restrict__ y) {
    int t = blockIdx.x, tid = threadIdx.x;
    __shared__ float rs[4], rs2[4];
    const float* xr = x + (size_t)t * DIM;
    float v[4], s = 0.f, s2 = 0.f;
#pragma unroll
    for (int i = 0; i < 4; i++) { v[i] = xr[tid + 128 * i]; s += v[i]; s2 += v[i] * v[i]; }
#pragma unroll
    for (int o = 16; o; o >>= 1) {
        s  += __shfl_down_sync(0xffffffffu, s,  o);
        s2 += __shfl_down_sync(0xffffffffu, s2, o);
    }
    if ((tid & 31) == 0) { rs[tid >> 5] = s; rs2[tid >> 5] = s2; }
    __syncthreads();
    float ts = rs[0] + rs[1] + rs[2] + rs[3];
    float ts2 = rs2[0] + rs2[1] + rs2[2] + rs2[3];
    float mean = ts * (1.f / DIM);
    float var = ts2 * (1.f / DIM) - mean * mean;
    float rstd = rsqrtf(var + 1e-5f);
#pragma unroll
    for (int i = 0; i < 4; i++) {
        int k = tid + 128 * i;
        y[(size_t)t * DIM + k] = __float2half_rn((v[i] - mean) * rstd * g[k] + bb[k]);
    }
}

// ---------------- attention (fp16 output) ----------------
__global__ void __launch_bounds__(128) attn_k() {
    extern __shared__ float asm_[];
    float* Ks  = asm_;
    float* Vs  = asm_ + 4096;
    float* scp = asm_ + 8192;

    int b = blockIdx.x, h = blockIdx.y;
    int tid = threadIdx.x;
    int q = tid & 63, half = tid >> 6;
    const float* base = g_qkv + (size_t)b * 64 * (3 * DIM);
    for (int i = tid; i < 64 * 64; i += 128) {
        int n = i >> 6, d2 = i & 63;
        Ks[i] = base[(size_t)n * (3 * DIM) + DIM     + h * 64 + d2];
        Vs[i] = base[(size_t)n * (3 * DIM) + 2 * DIM + h * 64 + d2];
    }
    float qreg[32];
    const float* qrow = base + (size_t)q * (3 * DIM) + h * 64 + half * 32;
#pragma unroll
    for (int j = 0; j < 32; j++) qreg[j] = qrow[j];
    __syncthreads();

#pragma unroll 4
    for (int k = 0; k < 64; k++) {
        float s = 0.f;
#pragma unroll
        for (int j = 0; j < 32; j++) s = fmaf(qreg[j], Ks[k * 64 + half * 32 + j], s);
        scp[half * 4096 + q * 64 + k] = s;
    }
    __syncthreads();

    if (half == 0) {
        float sc[64];
        float mx = -1e30f;
#pragma unroll
        for (int k = 0; k < 64; k++) {
            sc[k] = (scp[q * 64 + k] + scp[4096 + q * 64 + k]) * 0.125f;
            mx = fmaxf(mx, sc[k]);
        }
        float sum = 0.f;
#pragma unroll
        for (int k = 0; k < 64; k++) { sc[k] = expf(sc[k] - mx); sum += sc[k]; }
        float inv = 1.f / sum;
#pragma unroll
        for (int k = 0; k < 64; k++) scp[q * 64 + k] = sc[k] * inv;
    }
    __syncthreads();

    __half* orow = g_att_h + (size_t)(b * 64 + q) * DIM + h * 64 + half * 32;
#pragma unroll 4
    for (int d2 = 0; d2 < 32; d2++) {
        float o = 0.f;
#pragma unroll
        for (int k = 0; k < 64; k++) o = fmaf(scp[q * 64 + k], Vs[k * 64 + half * 32 + d2], o);
        orow[d2] = __float2half_rn(o);
    }
}

// ---------------- streams / events ----------------
#define DSM8 (3 * (ASZ + 32 * 136) * 4)
#define DSMH4 (3 * (HASZ + 32 * 72) * 2)
#define DSMA ((4096 + 4096 + 8192) * 4)
struct SfStreams {
    cudaStream_t s1, s2;
    cudaEvent_t e_root, e_pre, e_inits, e_sample, e_wout, e_t2, e_proj, e_outi;
    SfStreams() {
        cudaStreamCreateWithFlags(&s1, cudaStreamNonBlocking);
        cudaStreamCreateWithFlags(&s2, cudaStreamNonBlocking);
        cudaEventCreateWithFlags(&e_root,   cudaEventDisableTiming);
        cudaEventCreateWithFlags(&e_pre,    cudaEventDisableTiming);
        cudaEventCreateWithFlags(&e_inits,  cudaEventDisableTiming);
        cudaEventCreateWithFlags(&e_sample, cudaEventDisableTiming);
        cudaEventCreateWithFlags(&e_wout,   cudaEventDisableTiming);
        cudaEventCreateWithFlags(&e_t2,     cudaEventDisableTiming);
        cudaEventCreateWithFlags(&e_proj,   cudaEventDisableTiming);
        cudaEventCreateWithFlags(&e_outi,   cudaEventDisableTiming);
        cudaFuncSetAttribute(mma_gemm_t<8>, cudaFuncAttributeMaxDynamicSharedMemorySize, DSM8);
        cudaFuncSetAttribute(mma_gemm_h<4>, cudaFuncAttributeMaxDynamicSharedMemorySize, DSMH4);
        cudaFuncSetAttribute(mixmma_k, cudaFuncAttributeMaxDynamicSharedMemorySize, MXH_TOTAL);
        cudaFuncSetAttribute(attn_k, cudaFuncAttributeMaxDynamicSharedMemorySize, DSMA);
    }
};
static SfStreams g_sf;

// ---------------- launch ----------------
extern "C" void kernel_launch(void* const* d_in, const int* in_sizes, int n_in,
                              void* d_out, int out_size) {
    const float* token_embed = (const float*)d_in[0];
    const float* token_roi   = (const float*)d_in[1];
    const float* img_feat    = (const float*)d_in[2];
    const float* ln_off_g    = (const float*)d_in[3];
    const float* ln_off_b    = (const float*)d_in[4];
    const float* w_off       = (const float*)d_in[5];
    const float* off_bias    = (const float*)d_in[6];
    const float* ln_pg_g     = (const float*)d_in[7];
    const float* ln_pg_b     = (const float*)d_in[8];
    const float* w_pg1       = (const float*)d_in[9];
    const float* b_pg1       = (const float*)d_in[10];
    const float* w_pg2       = (const float*)d_in[11];
    const float* b_pg2       = (const float*)d_in[12];
    const float* m_beta      = (const float*)d_in[13];
    const float* s_beta      = (const float*)d_in[14];
    const float* w_out       = (const float*)d_in[15];
    const float* b_out       = (const float*)d_in[16];
    const float* ln1_g       = (const float*)d_in[17];
    const float* ln1_b       = (const float*)d_in[18];
    const float* w_qkv       = (const float*)d_in[19];
    const float* b_qkv       = (const float*)d_in[20];
    const float* w_proj      = (const float*)d_in[21];
    const float* b_proj      = (const float*)d_in[22];
    const float* ln2_g       = (const float*)d_in[23];
    const float* ln2_b       = (const float*)d_in[24];
    const float* w_fc1       = (const float*)d_in[25];
    const float* b_fc1       = (const float*)d_in[26];
    const float* w_fc2       = (const float*)d_in[27];
    const float* b_fc2       = (const float*)d_in[28];
    float* out = (float*)d_out;

    void* p;
    cudaGetSymbolAddress(&p, g_hidden);    float*  hidden = (float*)p;
    cudaGetSymbolAddress(&p, g_params_h);  __half* ph     = (__half*)p;
    cudaGetSymbolAddress(&p, g_h_h);       __half* hbuf   = (__half*)p;
    cudaGetSymbolAddress(&p, g_tok);       float*  tok    = (float*)p;
    cudaGetSymbolAddress(&p, g_tok2);      float*  tok2   = (float*)p;
    cudaGetSymbolAddress(&p, g_x_h);       __half* xbuf   = (__half*)p;
    cudaGetSymbolAddress(&p, g_qkv);       float*  qkv    = (float*)p;
    cudaGetSymbolAddress(&p, g_att_h);     __half* atth   = (__half*)p;
    cudaGetSymbolAddress(&p, g_ff_h);      __half* ffh    = (__half*)p;
    cudaGetSymbolAddress(&p, h_wout);      __half* hwout  = (__half*)p;
    cudaGetSymbolAddress(&p, h_wqkv);      __half* hwqkv  = (__half*)p;
    cudaGetSymbolAddress(&p, h_wproj);     __half* hwproj = (__half*)p;
    cudaGetSymbolAddress(&p, h_wfc1);      __half* hwfc1  = (__half*)p;
    cudaGetSymbolAddress(&p, h_wfc2);      __half* hwfc2  = (__half*)p;

    cudaStream_t s0 = 0, s1 = g_sf.s1, s2 = g_sf.s2;

    // ---- fork ----
    cudaEventRecord(g_sf.e_root, s0);
    cudaStreamWaitEvent(s1, g_sf.e_root, 0);
    cudaStreamWaitEvent(s2, g_sf.e_root, 0);

    // s0: pre_k -> params GEMM (tf32, fp16 out)
    pre_k<<<TKN, 128, 0, s0>>>(token_embed, token_roi, ln_off_g, ln_off_b, w_off, off_bias,
                               ln_pg_g, ln_pg_b, w_pg1, b_pg1);
    cudaEventRecord(g_sf.e_pre, s0);
    mma_gemm_t<8><<<dim3((TOTN + 127) / 128, TKN / 128, 1), 256, DSM8, s0>>>(
        hidden, w_pg2, b_pg2, ph, TKN, TOTN, PGN);

    // s1: weight fp16 conversion + fused init
    w2h_k<<<(WCT + 255) / 256, 256, 0, s1>>>(w_out, w_qkv, w_proj, w_fc1, w_fc2);
    init2_k<<<(TKN * DIM + TKN * 3 * DIM + 255) / 256, 256, 0, s1>>>(
        token_embed, b_out, b_qkv, tok, qkv);
    cudaEventRecord(g_sf.e_inits, s1);

    // s2: transpose, then sampling
    transpose_k<<<dim3((HGT * WID) / 32, CCH / 32, 8), 256, 0, s2>>>(img_feat);
    cudaStreamWaitEvent(s2, g_sf.e_pre, 0);
    sample_k<<<dim3(PPT, TKN), 64, 0, s2>>>();
    cudaEventRecord(g_sf.e_sample, s2);

    // s0: mixing (fp16 h output)
    cudaStreamWaitEvent(s0, g_sf.e_sample, 0);
    mixmma_k<<<TKN, 256, MXH_TOTAL, s0>>>(m_beta, s_beta);

    // s0: w_out GEMM (fp16, splitK16)
    cudaStreamWaitEvent(s0, g_sf.e_inits, 0);
    mma_gemm_h<4><<<dim3(DIM / 64, TKN / 128, 16), 256, DSMH4, s0>>>(
        hbuf, hwout, nullptr, tok, nullptr, TKN, DIM, PPT * CCH, 0);
    cudaEventRecord(g_sf.e_wout, s0);

    // s1: init_tok2
    cudaStreamWaitEvent(s1, g_sf.e_wout, 0);
    init_k<<<(TKN * DIM + 255) / 256, 256, 0, s1>>>(tok, b_proj, tok2, TKN * DIM, DIM);
    cudaEventRecord(g_sf.e_t2, s1);

    // s0: LN1 -> qkv (fp16, splitK4) -> attention
    ln_k<<<TKN, 128, 0, s0>>>(tok, ln1_g, ln1_b, xbuf);
    mma_gemm_h<4><<<dim3((3 * DIM) / 64, TKN / 128, 4), 256, DSMH4, s0>>>(
        xbuf, hwqkv, nullptr, qkv, nullptr, TKN, 3 * DIM, DIM, 0);
    attn_k<<<dim3(8, 8), 128, DSMA, s0>>>();
    // s0: proj (fp16, splitK8)
    cudaStreamWaitEvent(s0, g_sf.e_t2, 0);
    mma_gemm_h<4><<<dim3(DIM / 64, TKN / 128, 8), 256, DSMH4, s0>>>(
        atth, hwproj, nullptr, tok2, nullptr, TKN, DIM, DIM, 0);
    cudaEventRecord(g_sf.e_proj, s0);

    // s2: init_out
    cudaStreamWaitEvent(s2, g_sf.e_proj, 0);
    init_k<<<(TKN * DIM + 255) / 256, 256, 0, s2>>>(tok2, b_fc2, out, TKN * DIM, DIM);
    cudaEventRecord(g_sf.e_outi, s2);

    // s0: LN2 -> fc1 (fp16, fused bias+gelu, fp16 out) -> fc2 (fp16, splitK16)
    ln_k<<<TKN, 128, 0, s0>>>(tok2, ln2_g, ln2_b, xbuf);
    mma_gemm_h<4><<<dim3((4 * DIM) / 64, TKN / 128, 1), 256, DSMH4, s0>>>(
        xbuf, hwfc1, b_fc1, nullptr, ffh, TKN, 4 * DIM, DIM, 1);
    cudaStreamWaitEvent(s0, g_sf.e_outi, 0);
    mma_gemm_h<4><<<dim3(DIM / 64, TKN / 128, 16), 256, DSMH4, s0>>>(
        ffh, hwfc2, nullptr, out, nullptr, TKN, DIM, 4 * DIM, 0);
}